// round 13
// baseline (speedup 1.0000x reference)
#include <cuda_runtime.h>
#include <cuda_bf16.h>
#include <math.h>
#include <stdint.h>

#define S_LEN 4096
#define EMB   2048
#define NHEADS 16
#define NKVH   4
#define HDv    128
#define KVD    (NKVH * HDv)   // 512

// ------------------- scratch (device globals; no allocations) -------------------
__device__ float g_q [S_LEN * EMB];
__device__ float g_k [S_LEN * KVD];
__device__ float g_v [S_LEN * KVD];
__device__ float g_ao[S_LEN * EMB];
__device__ float g_cos[S_LEN * 64];
__device__ float g_sin[S_LEN * 64];
// split-bf16 operands (GEMM)
__device__ __nv_bfloat16 g_ah [S_LEN * EMB], g_al [S_LEN * EMB];
__device__ __nv_bfloat16 g_aoh[S_LEN * EMB], g_aol[S_LEN * EMB];
__device__ __nv_bfloat16 g_wqh[EMB * EMB], g_wql[EMB * EMB];
__device__ __nv_bfloat16 g_wkh[KVD * EMB], g_wkl[KVD * EMB];
__device__ __nv_bfloat16 g_wvh[KVD * EMB], g_wvl[KVD * EMB];
__device__ __nv_bfloat16 g_woh[EMB * EMB], g_wol[EMB * EMB];
// attention operands: Q/K hi-only; V split hi/lo
__device__ __nv_bfloat16 g_qh [NHEADS * S_LEN * HDv];                            // [h][s][d]
__device__ __nv_bfloat16 g_kh [NKVH * S_LEN * HDv];                              // [kvh][s][d]
__device__ __nv_bfloat16 g_vth[NKVH * HDv * S_LEN], g_vtl[NKVH * HDv * S_LEN];   // [kvh][d][s]

// ------------------- helpers -------------------
__device__ __forceinline__ uint32_t smem_u32(const void* p) {
    uint32_t a;
    asm("{ .reg .u64 t; cvta.to.shared.u64 t, %1; cvt.u32.u64 %0, t; }" : "=r"(a) : "l"(p));
    return a;
}
#define SMEM_SWZ(off) ((off) ^ (((off) >> 3) & 0x70))

#define LDSM4(r, a) \
    asm volatile("ldmatrix.sync.aligned.m8n8.x4.shared.b16 {%0,%1,%2,%3}, [%4];" \
        : "=r"((r)[0]), "=r"((r)[1]), "=r"((r)[2]), "=r"((r)[3]) : "r"(a))

#define MMA16816(d, a, b0v, b1v) \
    asm volatile("mma.sync.aligned.m16n8k16.row.col.f32.bf16.bf16.f32 " \
        "{%0,%1,%2,%3}, {%4,%5,%6,%7}, {%8,%9}, {%0,%1,%2,%3};" \
        : "+f"((d)[0]), "+f"((d)[1]), "+f"((d)[2]), "+f"((d)[3]) \
        : "r"((a)[0]), "r"((a)[1]), "r"((a)[2]), "r"((a)[3]), "r"(b0v), "r"(b1v))

#define CP_ASYNC16(s, g) \
    asm volatile("cp.async.cg.shared.global [%0], [%1], 16;" :: "r"(s), "l"(g))
#define CP_COMMIT() asm volatile("cp.async.commit_group;" ::: "memory")
#define CP_WAIT1()  asm volatile("cp.async.wait_group 1;" ::: "memory")
#define CP_WAIT0()  asm volatile("cp.async.wait_group 0;" ::: "memory")

// split a,b into packed bf16x2 hi and lo (lower half = a, upper half = b)
__device__ __forceinline__ void split2(float a, float b, uint32_t& ph, uint32_t& pl) {
    float ha = __bfloat162float(__float2bfloat16(a));
    float hb = __bfloat162float(__float2bfloat16(b));
    asm("cvt.rn.bf16x2.f32 %0, %1, %2;" : "=r"(ph) : "f"(hb), "f"(ha));
    asm("cvt.rn.bf16x2.f32 %0, %1, %2;" : "=r"(pl) : "f"(b - hb), "f"(a - ha));
}

// ------------------- split conversion: fp32 -> (hi, lo) bf16 -------------------
__global__ __launch_bounds__(256) void conv_split_kernel(
    const float* __restrict__ src, __nv_bfloat16* __restrict__ hi,
    __nv_bfloat16* __restrict__ lo, int n4)
{
    int i = blockIdx.x * 256 + threadIdx.x;
    if (i >= n4) return;
    float4 v = ((const float4*)src)[i];
    __nv_bfloat16 h0 = __float2bfloat16(v.x), h1 = __float2bfloat16(v.y);
    __nv_bfloat16 h2 = __float2bfloat16(v.z), h3 = __float2bfloat16(v.w);
    __nv_bfloat16 l0 = __float2bfloat16(v.x - __bfloat162float(h0));
    __nv_bfloat16 l1 = __float2bfloat16(v.y - __bfloat162float(h1));
    __nv_bfloat16 l2 = __float2bfloat16(v.z - __bfloat162float(h2));
    __nv_bfloat16 l3 = __float2bfloat16(v.w - __bfloat162float(h3));
    ((__nv_bfloat162*)hi)[i * 2]     = __nv_bfloat162(h0, h1);
    ((__nv_bfloat162*)hi)[i * 2 + 1] = __nv_bfloat162(h2, h3);
    ((__nv_bfloat162*)lo)[i * 2]     = __nv_bfloat162(l0, l1);
    ((__nv_bfloat162*)lo)[i * 2 + 1] = __nv_bfloat162(l2, l3);
}

// transpose + split: src [R',C] fp32 -> hi/lo [C,R] bf16
__global__ __launch_bounds__(256) void conv_split_t_kernel(
    const float* __restrict__ src, __nv_bfloat16* __restrict__ hi,
    __nv_bfloat16* __restrict__ lo, int R, int C)
{
    __shared__ float T[32][33];
    const int x = threadIdx.x, y = threadIdx.y;     // block (32, 8)
    const int c0 = blockIdx.x * 32, r0 = blockIdx.y * 32;
#pragma unroll
    for (int i = 0; i < 4; i++)
        T[y + 8 * i][x] = src[(size_t)(r0 + y + 8 * i) * C + c0 + x];
    __syncthreads();
#pragma unroll
    for (int i = 0; i < 4; i++) {
        int r = y + 8 * i;
        float v = T[x][r];
        __nv_bfloat16 h = __float2bfloat16(v);
        __nv_bfloat16 l = __float2bfloat16(v - __bfloat162float(h));
        size_t o = (size_t)(c0 + r) * R + r0 + x;
        hi[o] = h; lo[o] = l;
    }
}

// ------------------- mma.sync bf16 GEMM: SPLIT=3-pass fp32-accurate, !SPLIT=1-pass ----
// C[M,N] = A[M,K] @ Bt[N,K]^T. CTA 128x128, K-chunks of 64, 2-stage cp.async,
// 8 warps (2x4), warp tile 64x32.
#define TG_SMEM_SPLIT  (2 * 65536)
#define TG_SMEM_FAST   (2 * 32768)

template<bool SPLIT>
__global__ __launch_bounds__(256, 1)
void tgemm_kernel(const __nv_bfloat16* __restrict__ Ah, const __nv_bfloat16* __restrict__ Al,
                  const __nv_bfloat16* __restrict__ Bh, const __nv_bfloat16* __restrict__ Bl,
                  float* __restrict__ C, int N, int K)
{
    constexpr uint32_t STAGE = SPLIT ? 65536 : 32768;
    constexpr uint32_t BOFF  = SPLIT ? 32768 : 16384;   // B-hi offset within stage
    extern __shared__ char dsm[];
    const uint32_t sb = smem_u32(dsm);
    const int tid = threadIdx.x;
    const int wid = tid >> 5, lane = tid & 31;
    const int warp_m = wid >> 2, warp_n = wid & 3;
    const int row0 = blockIdx.y * 128;
    const int col0 = blockIdx.x * 128;

    const int crow = tid >> 3;
    const int cu = tid & 7;

    const int r16 = lane & 15;
    const int khB = (lane >> 4) * 16;
    const int a_row = warp_m * 64 + r16;
    const int b_row = warp_n * 32 + r16;

    float d[4][4][4];
#pragma unroll
    for (int mf = 0; mf < 4; mf++)
#pragma unroll
        for (int nf = 0; nf < 4; nf++)
#pragma unroll
            for (int j = 0; j < 4; j++) d[mf][nf][j] = 0.f;

    const int nch = K >> 6;

    {
        uint32_t s0 = sb;
#pragma unroll
        for (int t = 0; t < 4; t++) {
            int row = crow + t * 32;
            uint32_t so = SMEM_SWZ((uint32_t)(row * 128 + cu * 16));
            size_t ga = (size_t)(row0 + row) * K + cu * 8;
            size_t gb = (size_t)(col0 + row) * K + cu * 8;
            CP_ASYNC16(s0 + so,        (const char*)(Ah + ga));
            CP_ASYNC16(s0 + BOFF + so, (const char*)(Bh + gb));
            if (SPLIT) {
                CP_ASYNC16(s0 + 16384 + so, (const char*)(Al + ga));
                CP_ASYNC16(s0 + 49152 + so, (const char*)(Bl + gb));
            }
        }
        CP_COMMIT();
    }

    for (int c = 0; c < nch; c++) {
        if (c + 1 < nch) {
            uint32_t s1 = sb + ((c + 1) & 1) * STAGE;
            const int ke = (c + 1) * 64;
#pragma unroll
            for (int t = 0; t < 4; t++) {
                int row = crow + t * 32;
                uint32_t so = SMEM_SWZ((uint32_t)(row * 128 + cu * 16));
                size_t ga = (size_t)(row0 + row) * K + ke + cu * 8;
                size_t gb = (size_t)(col0 + row) * K + ke + cu * 8;
                CP_ASYNC16(s1 + so,        (const char*)(Ah + ga));
                CP_ASYNC16(s1 + BOFF + so, (const char*)(Bh + gb));
                if (SPLIT) {
                    CP_ASYNC16(s1 + 16384 + so, (const char*)(Al + ga));
                    CP_ASYNC16(s1 + 49152 + so, (const char*)(Bl + gb));
                }
            }
            CP_COMMIT();
            CP_WAIT1();
        } else {
            CP_WAIT0();
        }
        __syncthreads();

        const uint32_t buf = sb + (c & 1) * STAGE;
#pragma unroll
        for (int ks = 0; ks < 4; ks++) {
            uint32_t ah[4][4], al[4][4], bh[2][4], bl[2][4];
#pragma unroll
            for (int mf = 0; mf < 4; mf++) {
                uint32_t off = SMEM_SWZ((uint32_t)((a_row + mf * 16) * 128 + ks * 32 + khB));
                LDSM4(ah[mf], buf + off);
                if (SPLIT) LDSM4(al[mf], buf + 16384 + off);
            }
#pragma unroll
            for (int np = 0; np < 2; np++) {
                uint32_t off = SMEM_SWZ((uint32_t)((b_row + np * 16) * 128 + ks * 32 + khB));
                LDSM4(bh[np], buf + BOFF + off);
                if (SPLIT) LDSM4(bl[np], buf + 49152 + off);
            }
#pragma unroll
            for (int mf = 0; mf < 4; mf++)
#pragma unroll
                for (int nf = 0; nf < 4; nf++) {
                    const int np = nf >> 1, h = nf & 1;
                    MMA16816(d[mf][nf], ah[mf], bh[np][h], bh[np][2 + h]);
                    if (SPLIT) {
                        MMA16816(d[mf][nf], ah[mf], bl[np][h], bl[np][2 + h]);
                        MMA16816(d[mf][nf], al[mf], bh[np][h], bh[np][2 + h]);
                    }
                }
        }
        __syncthreads();
    }

    const int g = lane >> 2, tig = lane & 3;
#pragma unroll
    for (int mf = 0; mf < 4; mf++)
#pragma unroll
        for (int nf = 0; nf < 4; nf++) {
            int row = row0 + warp_m * 64 + mf * 16 + g;
            int col = col0 + warp_n * 32 + nf * 8 + tig * 2;
            *(float2*)&C[(size_t)row * N + col] = make_float2(d[mf][nf][0], d[mf][nf][1]);
            *(float2*)&C[(size_t)(row + 8) * N + col] = make_float2(d[mf][nf][2], d[mf][nf][3]);
        }
}

// ------------------- RoPE table (fp64 sincos once per (s,d)) -------------------
__global__ void rope_table_kernel(const int* __restrict__ pos_ids) {
    int s = blockIdx.x, d = threadIdx.x;
    double inv = pow(1000000.0, -(double)d / 64.0);
    double ang = (double)pos_ids[s] * inv;
    double sd, cd; sincos(ang, &sd, &cd);
    g_cos[s * 64 + d] = (float)cd;
    g_sin[s * 64 + d] = (float)sd;
}

// ------------------- RoPE apply -> bf16 (hi only) [h][s][d] -------------------
__global__ void rope_bf16_kernel(const float* __restrict__ src,
                                 __nv_bfloat16* __restrict__ oh,
                                 int ncols, float sc)
{
    int s = blockIdx.x, h = blockIdx.y, d = threadIdx.x;  // d in [0,64)
    float c  = g_cos[s * 64 + d];
    float sn = g_sin[s * 64 + d];
    const float* p = src + (size_t)s * ncols + h * HDv;
    float x0 = p[d], x1 = p[d + 64];
    size_t o = ((size_t)h * S_LEN + s) * HDv + d;
    oh[o]      = __float2bfloat16((x0 * c - x1 * sn) * sc);
    oh[o + 64] = __float2bfloat16((x1 * c + x0 * sn) * sc);
}

// ------------------- Flash attention: mma.sync, BM=128 (verified R11) -------------------
#define FQOFF   0
#define FKOFF   34816
#define FVOFF   69632
#define FA2_SMEM 143360

__global__ __launch_bounds__(256, 1) void flash_mma_kernel() {
    extern __shared__ char fsm[];
    const uint32_t sb = smem_u32(fsm);
    const int tid = threadIdx.x;
    const int wm = tid >> 5, lane = tid & 31;
    const int g = lane >> 2, tig = lane & 3;
    const int r16 = lane & 15;
    const int khB = (lane >> 4) * 16;
    const int h = blockIdx.y;
    const int qb = (int)gridDim.x - 1 - (int)blockIdx.x;  // long CTAs first
    const int q0 = qb * 128;
    const int kvh = h >> 2;

    const char* qhp = (const char*)(g_qh  + ((size_t)h * S_LEN + q0) * HDv);
    const char* khp = (const char*)(g_kh  + (size_t)kvh * S_LEN * HDv);
    const char* vhp = (const char*)(g_vth + (size_t)kvh * HDv * S_LEN);
    const char* vlp = (const char*)(g_vtl + (size_t)kvh * HDv * S_LEN);

    // Q tile (128 x 128 bf16, hi only)
#pragma unroll
    for (int t = 0; t < 8; t++) {
        int idx = tid + t * 256;
        int row = idx >> 4, u = idx & 15;
        CP_ASYNC16(sb + FQOFF + row * 272 + u * 16, qhp + row * 256 + u * 16);
    }
    // KV block 0
#pragma unroll
    for (int t = 0; t < 4; t++) {
        int idx = tid + t * 256;
        int row = idx >> 4, u = idx & 15;
        CP_ASYNC16(sb + FKOFF + row * 272 + u * 16, khp + row * 256 + u * 16);
        int vr = idx >> 3, vu = idx & 7;
        CP_ASYNC16(sb + FVOFF + vr * 144 + vu * 16,         vhp + (size_t)vr * (S_LEN * 2) + vu * 16);
        CP_ASYNC16(sb + FVOFF + 18432 + vr * 144 + vu * 16, vlp + (size_t)vr * (S_LEN * 2) + vu * 16);
    }
    CP_COMMIT();

    float m_run[2] = {-1e30f, -1e30f};
    float l_run[2] = {0.f, 0.f};
    float o[16][4];
#pragma unroll
    for (int i = 0; i < 16; i++) { o[i][0] = o[i][1] = o[i][2] = o[i][3] = 0.f; }

    const int nkb = 2 * qb + 2;

    for (int kb = 0; kb < nkb; kb++) {
        if (kb + 1 < nkb) {
            const size_t k0n = (size_t)(kb + 1) * 64;
            uint32_t KB = sb + FKOFF + ((kb + 1) & 1) * 17408;
            uint32_t VB = sb + FVOFF + ((kb + 1) & 1) * 36864;
#pragma unroll
            for (int t = 0; t < 4; t++) {
                int idx = tid + t * 256;
                int row = idx >> 4, u = idx & 15;
                CP_ASYNC16(KB + row * 272 + u * 16, khp + (k0n + row) * 256 + u * 16);
                int vr = idx >> 3, vu = idx & 7;
                CP_ASYNC16(VB + vr * 144 + vu * 16,         vhp + (size_t)vr * (S_LEN * 2) + k0n * 2 + vu * 16);
                CP_ASYNC16(VB + 18432 + vr * 144 + vu * 16, vlp + (size_t)vr * (S_LEN * 2) + k0n * 2 + vu * 16);
            }
            CP_COMMIT();
            CP_WAIT1();
        } else {
            CP_WAIT0();
        }
        __syncthreads();

        const int k0 = kb * 64;
        if (k0 <= q0 + wm * 16 + 15) {
            const uint32_t KB = sb + FKOFF + (kb & 1) * 17408;
            const uint32_t VB = sb + FVOFF + (kb & 1) * 36864;

            // ---- S = Q K^T (single-pass bf16) ----
            float s[8][4];
#pragma unroll
            for (int nf = 0; nf < 8; nf++) s[nf][0] = s[nf][1] = s[nf][2] = s[nf][3] = 0.f;
#pragma unroll
            for (int ks = 0; ks < 8; ks++) {
                uint32_t aqh[4], bkh[4][4];
                uint32_t qo = (uint32_t)((wm * 16 + r16) * 272 + ks * 32 + khB);
                LDSM4(aqh, sb + FQOFF + qo);
#pragma unroll
                for (int np = 0; np < 4; np++) {
                    uint32_t ko = (uint32_t)((np * 16 + r16) * 272 + ks * 32 + khB);
                    LDSM4(bkh[np], KB + ko);
                }
#pragma unroll
                for (int nf = 0; nf < 8; nf++) {
                    const int np = nf >> 1, hs = nf & 1;
                    MMA16816(s[nf], aqh, bkh[np][hs], bkh[np][2 + hs]);
                }
            }

            if (kb >= 2 * qb) {
#pragma unroll
                for (int nf = 0; nf < 8; nf++)
#pragma unroll
                    for (int j = 0; j < 4; j++) {
                        int r = q0 + wm * 16 + g + ((j >> 1) << 3);
                        int c = k0 + nf * 8 + tig * 2 + (j & 1);
                        if (c > r) s[nf][j] = -1e30f;
                    }
            }

            // ---- warp-local online softmax ----
            float rmx0 = -1e30f, rmx1 = -1e30f;
#pragma unroll
            for (int nf = 0; nf < 8; nf++) {
                rmx0 = fmaxf(rmx0, fmaxf(s[nf][0], s[nf][1]));
                rmx1 = fmaxf(rmx1, fmaxf(s[nf][2], s[nf][3]));
            }
            rmx0 = fmaxf(rmx0, __shfl_xor_sync(0xffffffffu, rmx0, 1));
            rmx0 = fmaxf(rmx0, __shfl_xor_sync(0xffffffffu, rmx0, 2));
            rmx1 = fmaxf(rmx1, __shfl_xor_sync(0xffffffffu, rmx1, 1));
            rmx1 = fmaxf(rmx1, __shfl_xor_sync(0xffffffffu, rmx1, 2));
            float mn0 = fmaxf(m_run[0], rmx0);
            float mn1 = fmaxf(m_run[1], rmx1);
            float fs0 = __expf(m_run[0] - mn0);
            float fs1 = __expf(m_run[1] - mn1);
            m_run[0] = mn0; m_run[1] = mn1;

            float sum0 = 0.f, sum1 = 0.f;
#pragma unroll
            for (int nf = 0; nf < 8; nf++) {
                s[nf][0] = __expf(s[nf][0] - mn0);
                s[nf][1] = __expf(s[nf][1] - mn0);
                s[nf][2] = __expf(s[nf][2] - mn1);
                s[nf][3] = __expf(s[nf][3] - mn1);
                sum0 += s[nf][0] + s[nf][1];
                sum1 += s[nf][2] + s[nf][3];
            }
            sum0 += __shfl_xor_sync(0xffffffffu, sum0, 1);
            sum0 += __shfl_xor_sync(0xffffffffu, sum0, 2);
            sum1 += __shfl_xor_sync(0xffffffffu, sum1, 1);
            sum1 += __shfl_xor_sync(0xffffffffu, sum1, 2);
            l_run[0] = l_run[0] * fs0 + sum0;
            l_run[1] = l_run[1] * fs1 + sum1;

#pragma unroll
            for (int i = 0; i < 16; i++) {
                o[i][0] *= fs0; o[i][1] *= fs0; o[i][2] *= fs1; o[i][3] *= fs1;
            }

            // ---- P A-frags (register reuse, split hi/lo) ----
            uint32_t aph[4][4], apl[4][4];
#pragma unroll
            for (int kk = 0; kk < 4; kk++) {
                const int nfA = 2 * kk, nfB = 2 * kk + 1;
                split2(s[nfA][0], s[nfA][1], aph[kk][0], apl[kk][0]);
                split2(s[nfA][2], s[nfA][3], aph[kk][1], apl[kk][1]);
                split2(s[nfB][0], s[nfB][1], aph[kk][2], apl[kk][2]);
                split2(s[nfB][2], s[nfB][3], aph[kk][3], apl[kk][3]);
            }

            // ---- O += P V (split 3-pass) ----
#pragma unroll
            for (int kk = 0; kk < 4; kk++) {
#pragma unroll
                for (int np = 0; np < 8; np++) {
                    uint32_t bvh[4], bvl[4];
                    uint32_t vo = (uint32_t)((np * 16 + r16) * 144 + kk * 32 + khB);
                    LDSM4(bvh, VB + vo);
                    LDSM4(bvl, VB + 18432 + vo);
#pragma unroll
                    for (int hs = 0; hs < 2; hs++) {
                        const int nd = np * 2 + hs;
                        MMA16816(o[nd], aph[kk], bvh[hs], bvh[2 + hs]);
                        MMA16816(o[nd], aph[kk], bvl[hs], bvl[2 + hs]);
                        MMA16816(o[nd], apl[kk], bvh[hs], bvh[2 + hs]);
                    }
                }
            }
        }
        __syncthreads();
    }

    // ---- epilogue ----
    float inv0 = 1.f / l_run[0], inv1 = 1.f / l_run[1];
    float* d0 = g_ao + (size_t)(q0 + wm * 16 + g) * EMB + h * HDv;
    float* d1 = g_ao + (size_t)(q0 + wm * 16 + g + 8) * EMB + h * HDv;
#pragma unroll
    for (int nd = 0; nd < 16; nd++) {
        int c = nd * 8 + tig * 2;
        *(float2*)(d0 + c) = make_float2(o[nd][0] * inv0, o[nd][1] * inv0);
        *(float2*)(d1 + c) = make_float2(o[nd][2] * inv1, o[nd][3] * inv1);
    }
}

// ------------------- launch -------------------
extern "C" void kernel_launch(void* const* d_in, const int* in_sizes, int n_in,
                              void* d_out, int out_size)
{
    const float* hs = (const float*)d_in[0];
    const float* Wq = (const float*)d_in[1];
    const float* Wk = (const float*)d_in[2];
    const float* Wv = (const float*)d_in[3];
    const float* Wo = (const float*)d_in[4];
    const int*   pos = (const int*)d_in[6];
    float* out = (float*)d_out;

    float *p_q, *p_k, *p_v, *p_ao;
    cudaGetSymbolAddress((void**)&p_q,  g_q);
    cudaGetSymbolAddress((void**)&p_k,  g_k);
    cudaGetSymbolAddress((void**)&p_v,  g_v);
    cudaGetSymbolAddress((void**)&p_ao, g_ao);
    __nv_bfloat16 *p_ah, *p_al, *p_aoh, *p_aol;
    __nv_bfloat16 *p_wqh, *p_wql, *p_wkh, *p_wkl, *p_wvh, *p_wvl, *p_woh, *p_wol;
    __nv_bfloat16 *p_qh, *p_kh, *p_vth, *p_vtl;
    cudaGetSymbolAddress((void**)&p_ah,  g_ah);
    cudaGetSymbolAddress((void**)&p_al,  g_al);
    cudaGetSymbolAddress((void**)&p_aoh, g_aoh);
    cudaGetSymbolAddress((void**)&p_aol, g_aol);
    cudaGetSymbolAddress((void**)&p_wqh, g_wqh);
    cudaGetSymbolAddress((void**)&p_wql, g_wql);
    cudaGetSymbolAddress((void**)&p_wkh, g_wkh);
    cudaGetSymbolAddress((void**)&p_wkl, g_wkl);
    cudaGetSymbolAddress((void**)&p_wvh, g_wvh);
    cudaGetSymbolAddress((void**)&p_wvl, g_wvl);
    cudaGetSymbolAddress((void**)&p_woh, g_woh);
    cudaGetSymbolAddress((void**)&p_wol, g_wol);
    cudaGetSymbolAddress((void**)&p_qh,  g_qh);
    cudaGetSymbolAddress((void**)&p_kh,  g_kh);
    cudaGetSymbolAddress((void**)&p_vth, g_vth);
    cudaGetSymbolAddress((void**)&p_vtl, g_vtl);

    cudaFuncSetAttribute(tgemm_kernel<true>,  cudaFuncAttributeMaxDynamicSharedMemorySize, TG_SMEM_SPLIT);
    cudaFuncSetAttribute(tgemm_kernel<false>, cudaFuncAttributeMaxDynamicSharedMemorySize, TG_SMEM_FAST);
    cudaFuncSetAttribute(flash_mma_kernel, cudaFuncAttributeMaxDynamicSharedMemorySize, FA2_SMEM);

    // 0) split conversions
    conv_split_kernel<<<(S_LEN * EMB / 4 + 255) / 256, 256>>>(hs, p_ah, p_al, S_LEN * EMB / 4);
    conv_split_t_kernel<<<dim3(EMB / 32, EMB / 32), dim3(32, 8)>>>(Wq, p_wqh, p_wql, EMB, EMB);
    conv_split_t_kernel<<<dim3(KVD / 32, EMB / 32), dim3(32, 8)>>>(Wk, p_wkh, p_wkl, EMB, KVD);
    conv_split_t_kernel<<<dim3(KVD / 32, EMB / 32), dim3(32, 8)>>>(Wv, p_wvh, p_wvl, EMB, KVD);
    conv_split_t_kernel<<<dim3(EMB / 32, EMB / 32), dim3(32, 8)>>>(Wo, p_woh, p_wol, EMB, EMB);

    // 1) projections (HMMA): Q/K single-pass bf16 (softmax abs-error argument), V 3-pass
    tgemm_kernel<false><<<dim3(EMB / 128, S_LEN / 128), 256, TG_SMEM_FAST>>>(p_ah, nullptr, p_wqh, nullptr, p_q, EMB, EMB);
    tgemm_kernel<false><<<dim3(KVD / 128, S_LEN / 128), 256, TG_SMEM_FAST>>>(p_ah, nullptr, p_wkh, nullptr, p_k, KVD, EMB);
    tgemm_kernel<true> <<<dim3(KVD / 128, S_LEN / 128), 256, TG_SMEM_SPLIT>>>(p_ah, p_al, p_wvh, p_wvl, p_v, KVD, EMB);

    // 2) RoPE -> bf16 attention operands (Q/K hi-only; V split)
    rope_table_kernel<<<S_LEN, 64>>>(pos);
    rope_bf16_kernel<<<dim3(S_LEN, NHEADS), 64>>>(p_q, p_qh, EMB, 0.08838834764831845f);
    rope_bf16_kernel<<<dim3(S_LEN, NKVH),  64>>>(p_k, p_kh, KVD, 1.0f);
    conv_split_t_kernel<<<dim3(KVD / 32, S_LEN / 32), dim3(32, 8)>>>(p_v, p_vth, p_vtl, S_LEN, KVD);

    // 3) causal flash attention (HMMA, BM=128, bf16 QK^T)
    flash_mma_kernel<<<dim3(S_LEN / 128, NHEADS), 256, FA2_SMEM>>>();

    // 4) output projection (HMMA, 3-pass)
    conv_split_kernel<<<(S_LEN * EMB / 4 + 255) / 256, 256>>>(p_ao, p_aoh, p_aol, S_LEN * EMB / 4);
    tgemm_kernel<true><<<dim3(EMB / 128, S_LEN / 128), 256, TG_SMEM_SPLIT>>>(p_aoh, p_aol, p_woh, p_wol, out, EMB, EMB);
}

// round 14
// speedup vs baseline: 1.5328x; 1.5328x over previous
#include <cuda_runtime.h>
#include <cuda_bf16.h>
#include <math.h>
#include <stdint.h>

#define S_LEN 4096
#define EMB   2048
#define NHEADS 16
#define NKVH   4
#define HDv    128
#define KVD    (NKVH * HDv)   // 512

// ------------------- scratch (device globals; no allocations) -------------------
__device__ float g_q [S_LEN * EMB];
__device__ float g_k [S_LEN * KVD];
__device__ float g_v [S_LEN * KVD];
__device__ float g_ao[S_LEN * EMB];
__device__ float g_cos[S_LEN * 64];
__device__ float g_sin[S_LEN * 64];
// split-bf16 operands (GEMM)
__device__ __nv_bfloat16 g_ah [S_LEN * EMB], g_al [S_LEN * EMB];
__device__ __nv_bfloat16 g_aoh[S_LEN * EMB], g_aol[S_LEN * EMB];
__device__ __nv_bfloat16 g_wqh[EMB * EMB], g_wql[EMB * EMB];
__device__ __nv_bfloat16 g_wkh[KVD * EMB], g_wkl[KVD * EMB];
__device__ __nv_bfloat16 g_wvh[KVD * EMB], g_wvl[KVD * EMB];
__device__ __nv_bfloat16 g_woh[EMB * EMB], g_wol[EMB * EMB];
// attention operands: Q/K hi-only; V split hi/lo
__device__ __nv_bfloat16 g_qh [NHEADS * S_LEN * HDv];                            // [h][s][d]
__device__ __nv_bfloat16 g_kh [NKVH * S_LEN * HDv];                              // [kvh][s][d]
__device__ __nv_bfloat16 g_vth[NKVH * HDv * S_LEN], g_vtl[NKVH * HDv * S_LEN];   // [kvh][d][s]

// ------------------- helpers -------------------
__device__ __forceinline__ uint32_t smem_u32(const void* p) {
    uint32_t a;
    asm("{ .reg .u64 t; cvta.to.shared.u64 t, %1; cvt.u32.u64 %0, t; }" : "=r"(a) : "l"(p));
    return a;
}
#define SMEM_SWZ(off) ((off) ^ (((off) >> 3) & 0x70))

#define LDSM4(r, a) \
    asm volatile("ldmatrix.sync.aligned.m8n8.x4.shared.b16 {%0,%1,%2,%3}, [%4];" \
        : "=r"((r)[0]), "=r"((r)[1]), "=r"((r)[2]), "=r"((r)[3]) : "r"(a))

#define MMA16816(d, a, b0v, b1v) \
    asm volatile("mma.sync.aligned.m16n8k16.row.col.f32.bf16.bf16.f32 " \
        "{%0,%1,%2,%3}, {%4,%5,%6,%7}, {%8,%9}, {%0,%1,%2,%3};" \
        : "+f"((d)[0]), "+f"((d)[1]), "+f"((d)[2]), "+f"((d)[3]) \
        : "r"((a)[0]), "r"((a)[1]), "r"((a)[2]), "r"((a)[3]), "r"(b0v), "r"(b1v))

#define CP_ASYNC16(s, g) \
    asm volatile("cp.async.cg.shared.global [%0], [%1], 16;" :: "r"(s), "l"(g))
#define CP_COMMIT() asm volatile("cp.async.commit_group;" ::: "memory")
#define CP_WAIT1()  asm volatile("cp.async.wait_group 1;" ::: "memory")
#define CP_WAIT0()  asm volatile("cp.async.wait_group 0;" ::: "memory")

// split a,b into packed bf16x2 hi and lo (lower half = a, upper half = b)
__device__ __forceinline__ void split2(float a, float b, uint32_t& ph, uint32_t& pl) {
    float ha = __bfloat162float(__float2bfloat16(a));
    float hb = __bfloat162float(__float2bfloat16(b));
    asm("cvt.rn.bf16x2.f32 %0, %1, %2;" : "=r"(ph) : "f"(hb), "f"(ha));
    asm("cvt.rn.bf16x2.f32 %0, %1, %2;" : "=r"(pl) : "f"(b - hb), "f"(a - ha));
}

// ------------------- split conversion: fp32 -> (hi, lo) bf16 -------------------
__global__ __launch_bounds__(256) void conv_split_kernel(
    const float* __restrict__ src, __nv_bfloat16* __restrict__ hi,
    __nv_bfloat16* __restrict__ lo, int n4)
{
    int i = blockIdx.x * 256 + threadIdx.x;
    if (i >= n4) return;
    float4 v = ((const float4*)src)[i];
    __nv_bfloat16 h0 = __float2bfloat16(v.x), h1 = __float2bfloat16(v.y);
    __nv_bfloat16 h2 = __float2bfloat16(v.z), h3 = __float2bfloat16(v.w);
    __nv_bfloat16 l0 = __float2bfloat16(v.x - __bfloat162float(h0));
    __nv_bfloat16 l1 = __float2bfloat16(v.y - __bfloat162float(h1));
    __nv_bfloat16 l2 = __float2bfloat16(v.z - __bfloat162float(h2));
    __nv_bfloat16 l3 = __float2bfloat16(v.w - __bfloat162float(h3));
    ((__nv_bfloat162*)hi)[i * 2]     = __nv_bfloat162(h0, h1);
    ((__nv_bfloat162*)hi)[i * 2 + 1] = __nv_bfloat162(h2, h3);
    ((__nv_bfloat162*)lo)[i * 2]     = __nv_bfloat162(l0, l1);
    ((__nv_bfloat162*)lo)[i * 2 + 1] = __nv_bfloat162(l2, l3);
}

// transpose + split: src [R',C] fp32 -> hi/lo [C,R] bf16
__global__ __launch_bounds__(256) void conv_split_t_kernel(
    const float* __restrict__ src, __nv_bfloat16* __restrict__ hi,
    __nv_bfloat16* __restrict__ lo, int R, int C)
{
    __shared__ float T[32][33];
    const int x = threadIdx.x, y = threadIdx.y;     // block (32, 8)
    const int c0 = blockIdx.x * 32, r0 = blockIdx.y * 32;
#pragma unroll
    for (int i = 0; i < 4; i++)
        T[y + 8 * i][x] = src[(size_t)(r0 + y + 8 * i) * C + c0 + x];
    __syncthreads();
#pragma unroll
    for (int i = 0; i < 4; i++) {
        int r = y + 8 * i;
        float v = T[x][r];
        __nv_bfloat16 h = __float2bfloat16(v);
        __nv_bfloat16 l = __float2bfloat16(v - __bfloat162float(h));
        size_t o = (size_t)(c0 + r) * R + r0 + x;
        hi[o] = h; lo[o] = l;
    }
}

// ------------------- mma.sync bf16 GEMM: SPLIT=3-pass fp32-accurate, !SPLIT=1-pass ----
// C[M,N] = A[M,K] @ Bt[N,K]^T. CTA 128x128, K-chunks of 64, 2-stage cp.async,
// 8 warps (2x4), warp tile 64x32.
#define TG_SMEM_SPLIT  (2 * 65536)
#define TG_SMEM_FAST   (2 * 32768)

template<bool SPLIT>
__global__ __launch_bounds__(256, 1)
void tgemm_kernel(const __nv_bfloat16* __restrict__ Ah, const __nv_bfloat16* __restrict__ Al,
                  const __nv_bfloat16* __restrict__ Bh, const __nv_bfloat16* __restrict__ Bl,
                  float* __restrict__ C, int N, int K)
{
    constexpr uint32_t STAGE = SPLIT ? 65536 : 32768;
    constexpr uint32_t BOFF  = SPLIT ? 32768 : 16384;   // B-hi offset within stage
    extern __shared__ char dsm[];
    const uint32_t sb = smem_u32(dsm);
    const int tid = threadIdx.x;
    const int wid = tid >> 5, lane = tid & 31;
    const int warp_m = wid >> 2, warp_n = wid & 3;
    const int row0 = blockIdx.y * 128;
    const int col0 = blockIdx.x * 128;

    const int crow = tid >> 3;
    const int cu = tid & 7;

    const int r16 = lane & 15;
    const int khB = (lane >> 4) * 16;
    const int a_row = warp_m * 64 + r16;
    const int b_row = warp_n * 32 + r16;

    float d[4][4][4];
#pragma unroll
    for (int mf = 0; mf < 4; mf++)
#pragma unroll
        for (int nf = 0; nf < 4; nf++)
#pragma unroll
            for (int j = 0; j < 4; j++) d[mf][nf][j] = 0.f;

    const int nch = K >> 6;

    {
        uint32_t s0 = sb;
#pragma unroll
        for (int t = 0; t < 4; t++) {
            int row = crow + t * 32;
            uint32_t so = SMEM_SWZ((uint32_t)(row * 128 + cu * 16));
            size_t ga = (size_t)(row0 + row) * K + cu * 8;
            size_t gb = (size_t)(col0 + row) * K + cu * 8;
            CP_ASYNC16(s0 + so,        (const char*)(Ah + ga));
            CP_ASYNC16(s0 + BOFF + so, (const char*)(Bh + gb));
            if (SPLIT) {
                CP_ASYNC16(s0 + 16384 + so, (const char*)(Al + ga));
                CP_ASYNC16(s0 + 49152 + so, (const char*)(Bl + gb));
            }
        }
        CP_COMMIT();
    }

    for (int c = 0; c < nch; c++) {
        if (c + 1 < nch) {
            uint32_t s1 = sb + ((c + 1) & 1) * STAGE;
            const int ke = (c + 1) * 64;
#pragma unroll
            for (int t = 0; t < 4; t++) {
                int row = crow + t * 32;
                uint32_t so = SMEM_SWZ((uint32_t)(row * 128 + cu * 16));
                size_t ga = (size_t)(row0 + row) * K + ke + cu * 8;
                size_t gb = (size_t)(col0 + row) * K + ke + cu * 8;
                CP_ASYNC16(s1 + so,        (const char*)(Ah + ga));
                CP_ASYNC16(s1 + BOFF + so, (const char*)(Bh + gb));
                if (SPLIT) {
                    CP_ASYNC16(s1 + 16384 + so, (const char*)(Al + ga));
                    CP_ASYNC16(s1 + 49152 + so, (const char*)(Bl + gb));
                }
            }
            CP_COMMIT();
            CP_WAIT1();
        } else {
            CP_WAIT0();
        }
        __syncthreads();

        const uint32_t buf = sb + (c & 1) * STAGE;
#pragma unroll
        for (int ks = 0; ks < 4; ks++) {
            uint32_t ah[4][4], al[4][4], bh[2][4], bl[2][4];
#pragma unroll
            for (int mf = 0; mf < 4; mf++) {
                uint32_t off = SMEM_SWZ((uint32_t)((a_row + mf * 16) * 128 + ks * 32 + khB));
                LDSM4(ah[mf], buf + off);
                if (SPLIT) LDSM4(al[mf], buf + 16384 + off);
            }
#pragma unroll
            for (int np = 0; np < 2; np++) {
                uint32_t off = SMEM_SWZ((uint32_t)((b_row + np * 16) * 128 + ks * 32 + khB));
                LDSM4(bh[np], buf + BOFF + off);
                if (SPLIT) LDSM4(bl[np], buf + 49152 + off);
            }
#pragma unroll
            for (int mf = 0; mf < 4; mf++)
#pragma unroll
                for (int nf = 0; nf < 4; nf++) {
                    const int np = nf >> 1, h = nf & 1;
                    MMA16816(d[mf][nf], ah[mf], bh[np][h], bh[np][2 + h]);
                    if (SPLIT) {
                        MMA16816(d[mf][nf], ah[mf], bl[np][h], bl[np][2 + h]);
                        MMA16816(d[mf][nf], al[mf], bh[np][h], bh[np][2 + h]);
                    }
                }
        }
        __syncthreads();
    }

    const int g = lane >> 2, tig = lane & 3;
#pragma unroll
    for (int mf = 0; mf < 4; mf++)
#pragma unroll
        for (int nf = 0; nf < 4; nf++) {
            int row = row0 + warp_m * 64 + mf * 16 + g;
            int col = col0 + warp_n * 32 + nf * 8 + tig * 2;
            *(float2*)&C[(size_t)row * N + col] = make_float2(d[mf][nf][0], d[mf][nf][1]);
            *(float2*)&C[(size_t)(row + 8) * N + col] = make_float2(d[mf][nf][2], d[mf][nf][3]);
        }
}

// ------------------- RoPE table (fp64 sincos once per (s,d)) -------------------
__global__ void rope_table_kernel(const int* __restrict__ pos_ids) {
    int s = blockIdx.x, d = threadIdx.x;
    double inv = pow(1000000.0, -(double)d / 64.0);
    double ang = (double)pos_ids[s] * inv;
    double sd, cd; sincos(ang, &sd, &cd);
    g_cos[s * 64 + d] = (float)cd;
    g_sin[s * 64 + d] = (float)sd;
}

// ------------------- RoPE apply -> bf16 (hi only) [h][s][d] -------------------
__global__ void rope_bf16_kernel(const float* __restrict__ src,
                                 __nv_bfloat16* __restrict__ oh,
                                 int ncols, float sc)
{
    int s = blockIdx.x, h = blockIdx.y, d = threadIdx.x;  // d in [0,64)
    float c  = g_cos[s * 64 + d];
    float sn = g_sin[s * 64 + d];
    const float* p = src + (size_t)s * ncols + h * HDv;
    float x0 = p[d], x1 = p[d + 64];
    size_t o = ((size_t)h * S_LEN + s) * HDv + d;
    oh[o]      = __float2bfloat16((x0 * c - x1 * sn) * sc);
    oh[o + 64] = __float2bfloat16((x1 * c + x0 * sn) * sc);
}

// ------------------- Flash attention: mma.sync, BM=128 (verified R11) -------------------
#define FQOFF   0
#define FKOFF   34816
#define FVOFF   69632
#define FA2_SMEM 143360

__global__ __launch_bounds__(256, 1) void flash_mma_kernel() {
    extern __shared__ char fsm[];
    const uint32_t sb = smem_u32(fsm);
    const int tid = threadIdx.x;
    const int wm = tid >> 5, lane = tid & 31;
    const int g = lane >> 2, tig = lane & 3;
    const int r16 = lane & 15;
    const int khB = (lane >> 4) * 16;
    const int h = blockIdx.y;
    const int qb = (int)gridDim.x - 1 - (int)blockIdx.x;  // long CTAs first
    const int q0 = qb * 128;
    const int kvh = h >> 2;

    const char* qhp = (const char*)(g_qh  + ((size_t)h * S_LEN + q0) * HDv);
    const char* khp = (const char*)(g_kh  + (size_t)kvh * S_LEN * HDv);
    const char* vhp = (const char*)(g_vth + (size_t)kvh * HDv * S_LEN);
    const char* vlp = (const char*)(g_vtl + (size_t)kvh * HDv * S_LEN);

    // Q tile (128 x 128 bf16, hi only)
#pragma unroll
    for (int t = 0; t < 8; t++) {
        int idx = tid + t * 256;
        int row = idx >> 4, u = idx & 15;
        CP_ASYNC16(sb + FQOFF + row * 272 + u * 16, qhp + row * 256 + u * 16);
    }
    // KV block 0
#pragma unroll
    for (int t = 0; t < 4; t++) {
        int idx = tid + t * 256;
        int row = idx >> 4, u = idx & 15;
        CP_ASYNC16(sb + FKOFF + row * 272 + u * 16, khp + row * 256 + u * 16);
        int vr = idx >> 3, vu = idx & 7;
        CP_ASYNC16(sb + FVOFF + vr * 144 + vu * 16,         vhp + (size_t)vr * (S_LEN * 2) + vu * 16);
        CP_ASYNC16(sb + FVOFF + 18432 + vr * 144 + vu * 16, vlp + (size_t)vr * (S_LEN * 2) + vu * 16);
    }
    CP_COMMIT();

    float m_run[2] = {-1e30f, -1e30f};
    float l_run[2] = {0.f, 0.f};
    float o[16][4];
#pragma unroll
    for (int i = 0; i < 16; i++) { o[i][0] = o[i][1] = o[i][2] = o[i][3] = 0.f; }

    const int nkb = 2 * qb + 2;

    for (int kb = 0; kb < nkb; kb++) {
        if (kb + 1 < nkb) {
            const size_t k0n = (size_t)(kb + 1) * 64;
            uint32_t KB = sb + FKOFF + ((kb + 1) & 1) * 17408;
            uint32_t VB = sb + FVOFF + ((kb + 1) & 1) * 36864;
#pragma unroll
            for (int t = 0; t < 4; t++) {
                int idx = tid + t * 256;
                int row = idx >> 4, u = idx & 15;
                CP_ASYNC16(KB + row * 272 + u * 16, khp + (k0n + row) * 256 + u * 16);
                int vr = idx >> 3, vu = idx & 7;
                CP_ASYNC16(VB + vr * 144 + vu * 16,         vhp + (size_t)vr * (S_LEN * 2) + k0n * 2 + vu * 16);
                CP_ASYNC16(VB + 18432 + vr * 144 + vu * 16, vlp + (size_t)vr * (S_LEN * 2) + k0n * 2 + vu * 16);
            }
            CP_COMMIT();
            CP_WAIT1();
        } else {
            CP_WAIT0();
        }
        __syncthreads();

        const int k0 = kb * 64;
        if (k0 <= q0 + wm * 16 + 15) {
            const uint32_t KB = sb + FKOFF + (kb & 1) * 17408;
            const uint32_t VB = sb + FVOFF + (kb & 1) * 36864;

            // ---- S = Q K^T (single-pass bf16) ----
            float s[8][4];
#pragma unroll
            for (int nf = 0; nf < 8; nf++) s[nf][0] = s[nf][1] = s[nf][2] = s[nf][3] = 0.f;
#pragma unroll
            for (int ks = 0; ks < 8; ks++) {
                uint32_t aqh[4], bkh[4][4];
                uint32_t qo = (uint32_t)((wm * 16 + r16) * 272 + ks * 32 + khB);
                LDSM4(aqh, sb + FQOFF + qo);
#pragma unroll
                for (int np = 0; np < 4; np++) {
                    uint32_t ko = (uint32_t)((np * 16 + r16) * 272 + ks * 32 + khB);
                    LDSM4(bkh[np], KB + ko);
                }
#pragma unroll
                for (int nf = 0; nf < 8; nf++) {
                    const int np = nf >> 1, hs = nf & 1;
                    MMA16816(s[nf], aqh, bkh[np][hs], bkh[np][2 + hs]);
                }
            }

            if (kb >= 2 * qb) {
#pragma unroll
                for (int nf = 0; nf < 8; nf++)
#pragma unroll
                    for (int j = 0; j < 4; j++) {
                        int r = q0 + wm * 16 + g + ((j >> 1) << 3);
                        int c = k0 + nf * 8 + tig * 2 + (j & 1);
                        if (c > r) s[nf][j] = -1e30f;
                    }
            }

            // ---- warp-local online softmax ----
            float rmx0 = -1e30f, rmx1 = -1e30f;
#pragma unroll
            for (int nf = 0; nf < 8; nf++) {
                rmx0 = fmaxf(rmx0, fmaxf(s[nf][0], s[nf][1]));
                rmx1 = fmaxf(rmx1, fmaxf(s[nf][2], s[nf][3]));
            }
            rmx0 = fmaxf(rmx0, __shfl_xor_sync(0xffffffffu, rmx0, 1));
            rmx0 = fmaxf(rmx0, __shfl_xor_sync(0xffffffffu, rmx0, 2));
            rmx1 = fmaxf(rmx1, __shfl_xor_sync(0xffffffffu, rmx1, 1));
            rmx1 = fmaxf(rmx1, __shfl_xor_sync(0xffffffffu, rmx1, 2));
            float mn0 = fmaxf(m_run[0], rmx0);
            float mn1 = fmaxf(m_run[1], rmx1);
            float fs0 = __expf(m_run[0] - mn0);
            float fs1 = __expf(m_run[1] - mn1);
            m_run[0] = mn0; m_run[1] = mn1;

            float sum0 = 0.f, sum1 = 0.f;
#pragma unroll
            for (int nf = 0; nf < 8; nf++) {
                s[nf][0] = __expf(s[nf][0] - mn0);
                s[nf][1] = __expf(s[nf][1] - mn0);
                s[nf][2] = __expf(s[nf][2] - mn1);
                s[nf][3] = __expf(s[nf][3] - mn1);
                sum0 += s[nf][0] + s[nf][1];
                sum1 += s[nf][2] + s[nf][3];
            }
            sum0 += __shfl_xor_sync(0xffffffffu, sum0, 1);
            sum0 += __shfl_xor_sync(0xffffffffu, sum0, 2);
            sum1 += __shfl_xor_sync(0xffffffffu, sum1, 1);
            sum1 += __shfl_xor_sync(0xffffffffu, sum1, 2);
            l_run[0] = l_run[0] * fs0 + sum0;
            l_run[1] = l_run[1] * fs1 + sum1;

#pragma unroll
            for (int i = 0; i < 16; i++) {
                o[i][0] *= fs0; o[i][1] *= fs0; o[i][2] *= fs1; o[i][3] *= fs1;
            }

            // ---- P A-frags (register reuse, split hi/lo) ----
            uint32_t aph[4][4], apl[4][4];
#pragma unroll
            for (int kk = 0; kk < 4; kk++) {
                const int nfA = 2 * kk, nfB = 2 * kk + 1;
                split2(s[nfA][0], s[nfA][1], aph[kk][0], apl[kk][0]);
                split2(s[nfA][2], s[nfA][3], aph[kk][1], apl[kk][1]);
                split2(s[nfB][0], s[nfB][1], aph[kk][2], apl[kk][2]);
                split2(s[nfB][2], s[nfB][3], aph[kk][3], apl[kk][3]);
            }

            // ---- O += P V (split 3-pass) ----
#pragma unroll
            for (int kk = 0; kk < 4; kk++) {
#pragma unroll
                for (int np = 0; np < 8; np++) {
                    uint32_t bvh[4], bvl[4];
                    uint32_t vo = (uint32_t)((np * 16 + r16) * 144 + kk * 32 + khB);
                    LDSM4(bvh, VB + vo);
                    LDSM4(bvl, VB + 18432 + vo);
#pragma unroll
                    for (int hs = 0; hs < 2; hs++) {
                        const int nd = np * 2 + hs;
                        MMA16816(o[nd], aph[kk], bvh[hs], bvh[2 + hs]);
                        MMA16816(o[nd], aph[kk], bvl[hs], bvl[2 + hs]);
                        MMA16816(o[nd], apl[kk], bvh[hs], bvh[2 + hs]);
                    }
                }
            }
        }
        __syncthreads();
    }

    // ---- epilogue ----
    float inv0 = 1.f / l_run[0], inv1 = 1.f / l_run[1];
    float* d0 = g_ao + (size_t)(q0 + wm * 16 + g) * EMB + h * HDv;
    float* d1 = g_ao + (size_t)(q0 + wm * 16 + g + 8) * EMB + h * HDv;
#pragma unroll
    for (int nd = 0; nd < 16; nd++) {
        int c = nd * 8 + tig * 2;
        *(float2*)(d0 + c) = make_float2(o[nd][0] * inv0, o[nd][1] * inv0);
        *(float2*)(d1 + c) = make_float2(o[nd][2] * inv1, o[nd][3] * inv1);
    }
}

// ------------------- launch -------------------
extern "C" void kernel_launch(void* const* d_in, const int* in_sizes, int n_in,
                              void* d_out, int out_size)
{
    const float* hs = (const float*)d_in[0];
    const float* Wq = (const float*)d_in[1];
    const float* Wk = (const float*)d_in[2];
    const float* Wv = (const float*)d_in[3];
    const float* Wo = (const float*)d_in[4];
    const int*   pos = (const int*)d_in[6];
    float* out = (float*)d_out;

    float *p_q, *p_k, *p_v, *p_ao;
    cudaGetSymbolAddress((void**)&p_q,  g_q);
    cudaGetSymbolAddress((void**)&p_k,  g_k);
    cudaGetSymbolAddress((void**)&p_v,  g_v);
    cudaGetSymbolAddress((void**)&p_ao, g_ao);
    __nv_bfloat16 *p_ah, *p_al, *p_aoh, *p_aol;
    __nv_bfloat16 *p_wqh, *p_wql, *p_wkh, *p_wkl, *p_wvh, *p_wvl, *p_woh, *p_wol;
    __nv_bfloat16 *p_qh, *p_kh, *p_vth, *p_vtl;
    cudaGetSymbolAddress((void**)&p_ah,  g_ah);
    cudaGetSymbolAddress((void**)&p_al,  g_al);
    cudaGetSymbolAddress((void**)&p_aoh, g_aoh);
    cudaGetSymbolAddress((void**)&p_aol, g_aol);
    cudaGetSymbolAddress((void**)&p_wqh, g_wqh);
    cudaGetSymbolAddress((void**)&p_wql, g_wql);
    cudaGetSymbolAddress((void**)&p_wkh, g_wkh);
    cudaGetSymbolAddress((void**)&p_wkl, g_wkl);
    cudaGetSymbolAddress((void**)&p_wvh, g_wvh);
    cudaGetSymbolAddress((void**)&p_wvl, g_wvl);
    cudaGetSymbolAddress((void**)&p_woh, g_woh);
    cudaGetSymbolAddress((void**)&p_wol, g_wol);
    cudaGetSymbolAddress((void**)&p_qh,  g_qh);
    cudaGetSymbolAddress((void**)&p_kh,  g_kh);
    cudaGetSymbolAddress((void**)&p_vth, g_vth);
    cudaGetSymbolAddress((void**)&p_vtl, g_vtl);

    cudaFuncSetAttribute(tgemm_kernel<true>,  cudaFuncAttributeMaxDynamicSharedMemorySize, TG_SMEM_SPLIT);
    cudaFuncSetAttribute(tgemm_kernel<false>, cudaFuncAttributeMaxDynamicSharedMemorySize, TG_SMEM_FAST);
    cudaFuncSetAttribute(flash_mma_kernel, cudaFuncAttributeMaxDynamicSharedMemorySize, FA2_SMEM);

    // 0) split conversions
    conv_split_kernel<<<(S_LEN * EMB / 4 + 255) / 256, 256>>>(hs, p_ah, p_al, S_LEN * EMB / 4);
    conv_split_t_kernel<<<dim3(EMB / 32, EMB / 32), dim3(32, 8)>>>(Wq, p_wqh, p_wql, EMB, EMB);
    conv_split_t_kernel<<<dim3(KVD / 32, EMB / 32), dim3(32, 8)>>>(Wk, p_wkh, p_wkl, EMB, KVD);
    conv_split_t_kernel<<<dim3(KVD / 32, EMB / 32), dim3(32, 8)>>>(Wv, p_wvh, p_wvl, EMB, KVD);
    conv_split_t_kernel<<<dim3(EMB / 32, EMB / 32), dim3(32, 8)>>>(Wo, p_woh, p_wol, EMB, EMB);

    // 1) projections (HMMA): Q/K single-pass bf16 (softmax abs-error argument), V 3-pass
    tgemm_kernel<false><<<dim3(EMB / 128, S_LEN / 128), 256, TG_SMEM_FAST>>>(p_ah, nullptr, p_wqh, nullptr, p_q, EMB, EMB);
    tgemm_kernel<false><<<dim3(KVD / 128, S_LEN / 128), 256, TG_SMEM_FAST>>>(p_ah, nullptr, p_wkh, nullptr, p_k, KVD, EMB);
    tgemm_kernel<true> <<<dim3(KVD / 128, S_LEN / 128), 256, TG_SMEM_SPLIT>>>(p_ah, p_al, p_wvh, p_wvl, p_v, KVD, EMB);

    // 2) RoPE -> bf16 attention operands (Q/K hi-only; V split)
    rope_table_kernel<<<S_LEN, 64>>>(pos);
    rope_bf16_kernel<<<dim3(S_LEN, NHEADS), 64>>>(p_q, p_qh, EMB, 0.08838834764831845f);
    rope_bf16_kernel<<<dim3(S_LEN, NKVH),  64>>>(p_k, p_kh, KVD, 1.0f);
    conv_split_t_kernel<<<dim3(KVD / 32, S_LEN / 32), dim3(32, 8)>>>(p_v, p_vth, p_vtl, S_LEN, KVD);

    // 3) causal flash attention (HMMA, BM=128, bf16 QK^T)
    flash_mma_kernel<<<dim3(S_LEN / 128, NHEADS), 256, FA2_SMEM>>>();

    // 4) output projection (HMMA, 3-pass)
    conv_split_kernel<<<(S_LEN * EMB / 4 + 255) / 256, 256>>>(p_ao, p_aoh, p_aol, S_LEN * EMB / 4);
    tgemm_kernel<true><<<dim3(EMB / 128, S_LEN / 128), 256, TG_SMEM_SPLIT>>>(p_aoh, p_aol, p_woh, p_wol, out, EMB, EMB);
}

// round 16
// speedup vs baseline: 1.5958x; 1.0411x over previous
#include <cuda_runtime.h>
#include <cuda_bf16.h>
#include <math.h>
#include <stdint.h>

#define S_LEN 4096
#define EMB   2048
#define NHEADS 16
#define NKVH   4
#define HDv    128
#define KVD    (NKVH * HDv)   // 512

// ------------------- scratch (device globals; no allocations) -------------------
__device__ float g_q [S_LEN * EMB];
__device__ float g_k [S_LEN * KVD];
__device__ float g_v [S_LEN * KVD];
__device__ float g_cos[S_LEN * 64];
__device__ float g_sin[S_LEN * 64];
// split-bf16 operands (GEMM)
__device__ __nv_bfloat16 g_ah [S_LEN * EMB], g_al [S_LEN * EMB];
__device__ __nv_bfloat16 g_aoh[S_LEN * EMB], g_aol[S_LEN * EMB];   // flash writes these directly
__device__ __nv_bfloat16 g_wqh[EMB * EMB], g_wql[EMB * EMB];
__device__ __nv_bfloat16 g_wkh[KVD * EMB], g_wkl[KVD * EMB];
__device__ __nv_bfloat16 g_wvh[KVD * EMB], g_wvl[KVD * EMB];
__device__ __nv_bfloat16 g_woh[EMB * EMB], g_wol[EMB * EMB];
// attention operands: Q/K hi-only; V split hi/lo
__device__ __nv_bfloat16 g_qh [NHEADS * S_LEN * HDv];                            // [h][s][d]
__device__ __nv_bfloat16 g_kh [NKVH * S_LEN * HDv];                              // [kvh][s][d]
__device__ __nv_bfloat16 g_vth[NKVH * HDv * S_LEN], g_vtl[NKVH * HDv * S_LEN];   // [kvh][d][s]

// ------------------- helpers -------------------
__device__ __forceinline__ uint32_t smem_u32(const void* p) {
    uint32_t a;
    asm("{ .reg .u64 t; cvta.to.shared.u64 t, %1; cvt.u32.u64 %0, t; }" : "=r"(a) : "l"(p));
    return a;
}
#define SMEM_SWZ(off) ((off) ^ (((off) >> 3) & 0x70))

#define LDSM4(r, a) \
    asm volatile("ldmatrix.sync.aligned.m8n8.x4.shared.b16 {%0,%1,%2,%3}, [%4];" \
        : "=r"((r)[0]), "=r"((r)[1]), "=r"((r)[2]), "=r"((r)[3]) : "r"(a))

#define MMA16816(d, a, b0v, b1v) \
    asm volatile("mma.sync.aligned.m16n8k16.row.col.f32.bf16.bf16.f32 " \
        "{%0,%1,%2,%3}, {%4,%5,%6,%7}, {%8,%9}, {%0,%1,%2,%3};" \
        : "+f"((d)[0]), "+f"((d)[1]), "+f"((d)[2]), "+f"((d)[3]) \
        : "r"((a)[0]), "r"((a)[1]), "r"((a)[2]), "r"((a)[3]), "r"(b0v), "r"(b1v))

#define CP_ASYNC16(s, g) \
    asm volatile("cp.async.cg.shared.global [%0], [%1], 16;" :: "r"(s), "l"(g))
#define CP_COMMIT() asm volatile("cp.async.commit_group;" ::: "memory")
#define CP_WAIT1()  asm volatile("cp.async.wait_group 1;" ::: "memory")
#define CP_WAIT0()  asm volatile("cp.async.wait_group 0;" ::: "memory")

// split a,b into packed bf16x2 hi and lo (lower half = a, upper half = b)
__device__ __forceinline__ void split2(float a, float b, uint32_t& ph, uint32_t& pl) {
    float ha = __bfloat162float(__float2bfloat16(a));
    float hb = __bfloat162float(__float2bfloat16(b));
    asm("cvt.rn.bf16x2.f32 %0, %1, %2;" : "=r"(ph) : "f"(hb), "f"(ha));
    asm("cvt.rn.bf16x2.f32 %0, %1, %2;" : "=r"(pl) : "f"(b - hb), "f"(a - ha));
}

// ------------------- split conversion: fp32 -> (hi, lo) bf16 -------------------
__global__ __launch_bounds__(256) void conv_split_kernel(
    const float* __restrict__ src, __nv_bfloat16* __restrict__ hi,
    __nv_bfloat16* __restrict__ lo, int n4)
{
    int i = blockIdx.x * 256 + threadIdx.x;
    if (i >= n4) return;
    float4 v = ((const float4*)src)[i];
    __nv_bfloat16 h0 = __float2bfloat16(v.x), h1 = __float2bfloat16(v.y);
    __nv_bfloat16 h2 = __float2bfloat16(v.z), h3 = __float2bfloat16(v.w);
    __nv_bfloat16 l0 = __float2bfloat16(v.x - __bfloat162float(h0));
    __nv_bfloat16 l1 = __float2bfloat16(v.y - __bfloat162float(h1));
    __nv_bfloat16 l2 = __float2bfloat16(v.z - __bfloat162float(h2));
    __nv_bfloat16 l3 = __float2bfloat16(v.w - __bfloat162float(h3));
    ((__nv_bfloat162*)hi)[i * 2]     = __nv_bfloat162(h0, h1);
    ((__nv_bfloat162*)hi)[i * 2 + 1] = __nv_bfloat162(h2, h3);
    ((__nv_bfloat162*)lo)[i * 2]     = __nv_bfloat162(l0, l1);
    ((__nv_bfloat162*)lo)[i * 2 + 1] = __nv_bfloat162(l2, l3);
}

// transpose + split: src [R',C] fp32 -> hi/lo [C,R] bf16
__global__ __launch_bounds__(256) void conv_split_t_kernel(
    const float* __restrict__ src, __nv_bfloat16* __restrict__ hi,
    __nv_bfloat16* __restrict__ lo, int R, int C)
{
    __shared__ float T[32][33];
    const int x = threadIdx.x, y = threadIdx.y;     // block (32, 8)
    const int c0 = blockIdx.x * 32, r0 = blockIdx.y * 32;
#pragma unroll
    for (int i = 0; i < 4; i++)
        T[y + 8 * i][x] = src[(size_t)(r0 + y + 8 * i) * C + c0 + x];
    __syncthreads();
#pragma unroll
    for (int i = 0; i < 4; i++) {
        int r = y + 8 * i;
        float v = T[x][r];
        __nv_bfloat16 h = __float2bfloat16(v);
        __nv_bfloat16 l = __float2bfloat16(v - __bfloat162float(h));
        size_t o = (size_t)(c0 + r) * R + r0 + x;
        hi[o] = h; lo[o] = l;
    }
}

// ------------------- mma.sync bf16 GEMM: SPLIT=3-pass fp32-accurate, !SPLIT=1-pass ----
#define TG_SMEM_SPLIT  (2 * 65536)
#define TG_SMEM_FAST   (2 * 32768)

template<bool SPLIT>
__global__ __launch_bounds__(256, 1)
void tgemm_kernel(const __nv_bfloat16* __restrict__ Ah, const __nv_bfloat16* __restrict__ Al,
                  const __nv_bfloat16* __restrict__ Bh, const __nv_bfloat16* __restrict__ Bl,
                  float* __restrict__ C, int N, int K)
{
    constexpr uint32_t STAGE = SPLIT ? 65536 : 32768;
    constexpr uint32_t BOFF  = SPLIT ? 32768 : 16384;
    extern __shared__ char dsm[];
    const uint32_t sb = smem_u32(dsm);
    const int tid = threadIdx.x;
    const int wid = tid >> 5, lane = tid & 31;
    const int warp_m = wid >> 2, warp_n = wid & 3;
    const int row0 = blockIdx.y * 128;
    const int col0 = blockIdx.x * 128;

    const int crow = tid >> 3;
    const int cu = tid & 7;

    const int r16 = lane & 15;
    const int khB = (lane >> 4) * 16;
    const int a_row = warp_m * 64 + r16;
    const int b_row = warp_n * 32 + r16;

    float d[4][4][4];
#pragma unroll
    for (int mf = 0; mf < 4; mf++)
#pragma unroll
        for (int nf = 0; nf < 4; nf++)
#pragma unroll
            for (int j = 0; j < 4; j++) d[mf][nf][j] = 0.f;

    const int nch = K >> 6;

    {
        uint32_t s0 = sb;
#pragma unroll
        for (int t = 0; t < 4; t++) {
            int row = crow + t * 32;
            uint32_t so = SMEM_SWZ((uint32_t)(row * 128 + cu * 16));
            size_t ga = (size_t)(row0 + row) * K + cu * 8;
            size_t gb = (size_t)(col0 + row) * K + cu * 8;
            CP_ASYNC16(s0 + so,        (const char*)(Ah + ga));
            CP_ASYNC16(s0 + BOFF + so, (const char*)(Bh + gb));
            if (SPLIT) {
                CP_ASYNC16(s0 + 16384 + so, (const char*)(Al + ga));
                CP_ASYNC16(s0 + 49152 + so, (const char*)(Bl + gb));
            }
        }
        CP_COMMIT();
    }

    for (int c = 0; c < nch; c++) {
        if (c + 1 < nch) {
            uint32_t s1 = sb + ((c + 1) & 1) * STAGE;
            const int ke = (c + 1) * 64;
#pragma unroll
            for (int t = 0; t < 4; t++) {
                int row = crow + t * 32;
                uint32_t so = SMEM_SWZ((uint32_t)(row * 128 + cu * 16));
                size_t ga = (size_t)(row0 + row) * K + ke + cu * 8;
                size_t gb = (size_t)(col0 + row) * K + ke + cu * 8;
                CP_ASYNC16(s1 + so,        (const char*)(Ah + ga));
                CP_ASYNC16(s1 + BOFF + so, (const char*)(Bh + gb));
                if (SPLIT) {
                    CP_ASYNC16(s1 + 16384 + so, (const char*)(Al + ga));
                    CP_ASYNC16(s1 + 49152 + so, (const char*)(Bl + gb));
                }
            }
            CP_COMMIT();
            CP_WAIT1();
        } else {
            CP_WAIT0();
        }
        __syncthreads();

        const uint32_t buf = sb + (c & 1) * STAGE;
#pragma unroll
        for (int ks = 0; ks < 4; ks++) {
            uint32_t ah[4][4], al[4][4], bh[2][4], bl[2][4];
#pragma unroll
            for (int mf = 0; mf < 4; mf++) {
                uint32_t off = SMEM_SWZ((uint32_t)((a_row + mf * 16) * 128 + ks * 32 + khB));
                LDSM4(ah[mf], buf + off);
                if (SPLIT) LDSM4(al[mf], buf + 16384 + off);
            }
#pragma unroll
            for (int np = 0; np < 2; np++) {
                uint32_t off = SMEM_SWZ((uint32_t)((b_row + np * 16) * 128 + ks * 32 + khB));
                LDSM4(bh[np], buf + BOFF + off);
                if (SPLIT) LDSM4(bl[np], buf + 49152 + off);
            }
#pragma unroll
            for (int mf = 0; mf < 4; mf++)
#pragma unroll
                for (int nf = 0; nf < 4; nf++) {
                    const int np = nf >> 1, h = nf & 1;
                    MMA16816(d[mf][nf], ah[mf], bh[np][h], bh[np][2 + h]);
                    if (SPLIT) {
                        MMA16816(d[mf][nf], ah[mf], bl[np][h], bl[np][2 + h]);
                        MMA16816(d[mf][nf], al[mf], bh[np][h], bh[np][2 + h]);
                    }
                }
        }
        __syncthreads();
    }

    const int g = lane >> 2, tig = lane & 3;
#pragma unroll
    for (int mf = 0; mf < 4; mf++)
#pragma unroll
        for (int nf = 0; nf < 4; nf++) {
            int row = row0 + warp_m * 64 + mf * 16 + g;
            int col = col0 + warp_n * 32 + nf * 8 + tig * 2;
            *(float2*)&C[(size_t)row * N + col] = make_float2(d[mf][nf][0], d[mf][nf][1]);
            *(float2*)&C[(size_t)(row + 8) * N + col] = make_float2(d[mf][nf][2], d[mf][nf][3]);
        }
}

// ------------------- RoPE table (fp32, replicating reference op order) -------------------
__global__ void rope_table_kernel(const int* __restrict__ pos_ids) {
    int s = blockIdx.x, d = threadIdx.x;   // d in [0,64)
    float x = (float)d / 64.0f;            // exact (d/64, power-of-2 divisor)
    float inv = 1.0f / powf(1000000.0f, x);
    float ang = (float)pos_ids[s] * inv;
    float sn, c;
    sincosf(ang, &sn, &c);
    g_cos[s * 64 + d] = c;
    g_sin[s * 64 + d] = sn;
}

// ------------------- RoPE apply -> bf16 (hi only) [h][s][d] -------------------
__global__ void rope_bf16_kernel(const float* __restrict__ src,
                                 __nv_bfloat16* __restrict__ oh,
                                 int ncols, float sc)
{
    int s = blockIdx.x, h = blockIdx.y, d = threadIdx.x;  // d in [0,64)
    float c  = g_cos[s * 64 + d];
    float sn = g_sin[s * 64 + d];
    const float* p = src + (size_t)s * ncols + h * HDv;
    float x0 = p[d], x1 = p[d + 64];
    size_t o = ((size_t)h * S_LEN + s) * HDv + d;
    oh[o]      = __float2bfloat16((x0 * c - x1 * sn) * sc);
    oh[o + 64] = __float2bfloat16((x1 * c + x0 * sn) * sc);
}

// ------------------- Flash attention: mma.sync, BM=128 (verified R11/R14) -------------------
// Epilogue now writes split-bf16 attn-out (g_aoh/g_aol) directly.
#define FQOFF   0
#define FKOFF   34816
#define FVOFF   69632
#define FA2_SMEM 143360

__global__ __launch_bounds__(256, 1) void flash_mma_kernel() {
    extern __shared__ char fsm[];
    const uint32_t sb = smem_u32(fsm);
    const int tid = threadIdx.x;
    const int wm = tid >> 5, lane = tid & 31;
    const int g = lane >> 2, tig = lane & 3;
    const int r16 = lane & 15;
    const int khB = (lane >> 4) * 16;
    const int h = blockIdx.y;
    const int qb = (int)gridDim.x - 1 - (int)blockIdx.x;  // long CTAs first
    const int q0 = qb * 128;
    const int kvh = h >> 2;

    const char* qhp = (const char*)(g_qh  + ((size_t)h * S_LEN + q0) * HDv);
    const char* khp = (const char*)(g_kh  + (size_t)kvh * S_LEN * HDv);
    const char* vhp = (const char*)(g_vth + (size_t)kvh * HDv * S_LEN);
    const char* vlp = (const char*)(g_vtl + (size_t)kvh * HDv * S_LEN);

    // Q tile (128 x 128 bf16, hi only)
#pragma unroll
    for (int t = 0; t < 8; t++) {
        int idx = tid + t * 256;
        int row = idx >> 4, u = idx & 15;
        CP_ASYNC16(sb + FQOFF + row * 272 + u * 16, qhp + row * 256 + u * 16);
    }
    // KV block 0
#pragma unroll
    for (int t = 0; t < 4; t++) {
        int idx = tid + t * 256;
        int row = idx >> 4, u = idx & 15;
        CP_ASYNC16(sb + FKOFF + row * 272 + u * 16, khp + row * 256 + u * 16);
        int vr = idx >> 3, vu = idx & 7;
        CP_ASYNC16(sb + FVOFF + vr * 144 + vu * 16,         vhp + (size_t)vr * (S_LEN * 2) + vu * 16);
        CP_ASYNC16(sb + FVOFF + 18432 + vr * 144 + vu * 16, vlp + (size_t)vr * (S_LEN * 2) + vu * 16);
    }
    CP_COMMIT();

    float m_run[2] = {-1e30f, -1e30f};
    float l_run[2] = {0.f, 0.f};
    float o[16][4];
#pragma unroll
    for (int i = 0; i < 16; i++) { o[i][0] = o[i][1] = o[i][2] = o[i][3] = 0.f; }

    const int nkb = 2 * qb + 2;

    for (int kb = 0; kb < nkb; kb++) {
        if (kb + 1 < nkb) {
            const size_t k0n = (size_t)(kb + 1) * 64;
            uint32_t KB = sb + FKOFF + ((kb + 1) & 1) * 17408;
            uint32_t VB = sb + FVOFF + ((kb + 1) & 1) * 36864;
#pragma unroll
            for (int t = 0; t < 4; t++) {
                int idx = tid + t * 256;
                int row = idx >> 4, u = idx & 15;
                CP_ASYNC16(KB + row * 272 + u * 16, khp + (k0n + row) * 256 + u * 16);
                int vr = idx >> 3, vu = idx & 7;
                CP_ASYNC16(VB + vr * 144 + vu * 16,         vhp + (size_t)vr * (S_LEN * 2) + k0n * 2 + vu * 16);
                CP_ASYNC16(VB + 18432 + vr * 144 + vu * 16, vlp + (size_t)vr * (S_LEN * 2) + k0n * 2 + vu * 16);
            }
            CP_COMMIT();
            CP_WAIT1();
        } else {
            CP_WAIT0();
        }
        __syncthreads();

        const int k0 = kb * 64;
        if (k0 <= q0 + wm * 16 + 15) {
            const uint32_t KB = sb + FKOFF + (kb & 1) * 17408;
            const uint32_t VB = sb + FVOFF + (kb & 1) * 36864;

            // ---- S = Q K^T (single-pass bf16) ----
            float s[8][4];
#pragma unroll
            for (int nf = 0; nf < 8; nf++) s[nf][0] = s[nf][1] = s[nf][2] = s[nf][3] = 0.f;
#pragma unroll
            for (int ks = 0; ks < 8; ks++) {
                uint32_t aqh[4], bkh[4][4];
                uint32_t qo = (uint32_t)((wm * 16 + r16) * 272 + ks * 32 + khB);
                LDSM4(aqh, sb + FQOFF + qo);
#pragma unroll
                for (int np = 0; np < 4; np++) {
                    uint32_t ko = (uint32_t)((np * 16 + r16) * 272 + ks * 32 + khB);
                    LDSM4(bkh[np], KB + ko);
                }
#pragma unroll
                for (int nf = 0; nf < 8; nf++) {
                    const int np = nf >> 1, hs = nf & 1;
                    MMA16816(s[nf], aqh, bkh[np][hs], bkh[np][2 + hs]);
                }
            }

            if (kb >= 2 * qb) {
#pragma unroll
                for (int nf = 0; nf < 8; nf++)
#pragma unroll
                    for (int j = 0; j < 4; j++) {
                        int r = q0 + wm * 16 + g + ((j >> 1) << 3);
                        int c = k0 + nf * 8 + tig * 2 + (j & 1);
                        if (c > r) s[nf][j] = -1e30f;
                    }
            }

            // ---- warp-local online softmax ----
            float rmx0 = -1e30f, rmx1 = -1e30f;
#pragma unroll
            for (int nf = 0; nf < 8; nf++) {
                rmx0 = fmaxf(rmx0, fmaxf(s[nf][0], s[nf][1]));
                rmx1 = fmaxf(rmx1, fmaxf(s[nf][2], s[nf][3]));
            }
            rmx0 = fmaxf(rmx0, __shfl_xor_sync(0xffffffffu, rmx0, 1));
            rmx0 = fmaxf(rmx0, __shfl_xor_sync(0xffffffffu, rmx0, 2));
            rmx1 = fmaxf(rmx1, __shfl_xor_sync(0xffffffffu, rmx1, 1));
            rmx1 = fmaxf(rmx1, __shfl_xor_sync(0xffffffffu, rmx1, 2));
            float mn0 = fmaxf(m_run[0], rmx0);
            float mn1 = fmaxf(m_run[1], rmx1);
            float fs0 = __expf(m_run[0] - mn0);
            float fs1 = __expf(m_run[1] - mn1);
            m_run[0] = mn0; m_run[1] = mn1;

            float sum0 = 0.f, sum1 = 0.f;
#pragma unroll
            for (int nf = 0; nf < 8; nf++) {
                s[nf][0] = __expf(s[nf][0] - mn0);
                s[nf][1] = __expf(s[nf][1] - mn0);
                s[nf][2] = __expf(s[nf][2] - mn1);
                s[nf][3] = __expf(s[nf][3] - mn1);
                sum0 += s[nf][0] + s[nf][1];
                sum1 += s[nf][2] + s[nf][3];
            }
            sum0 += __shfl_xor_sync(0xffffffffu, sum0, 1);
            sum0 += __shfl_xor_sync(0xffffffffu, sum0, 2);
            sum1 += __shfl_xor_sync(0xffffffffu, sum1, 1);
            sum1 += __shfl_xor_sync(0xffffffffu, sum1, 2);
            l_run[0] = l_run[0] * fs0 + sum0;
            l_run[1] = l_run[1] * fs1 + sum1;

#pragma unroll
            for (int i = 0; i < 16; i++) {
                o[i][0] *= fs0; o[i][1] *= fs0; o[i][2] *= fs1; o[i][3] *= fs1;
            }

            // ---- P A-frags (register reuse, split hi/lo) ----
            uint32_t aph[4][4], apl[4][4];
#pragma unroll
            for (int kk = 0; kk < 4; kk++) {
                const int nfA = 2 * kk, nfB = 2 * kk + 1;
                split2(s[nfA][0], s[nfA][1], aph[kk][0], apl[kk][0]);
                split2(s[nfA][2], s[nfA][3], aph[kk][1], apl[kk][1]);
                split2(s[nfB][0], s[nfB][1], aph[kk][2], apl[kk][2]);
                split2(s[nfB][2], s[nfB][3], aph[kk][3], apl[kk][3]);
            }

            // ---- O += P V (split 3-pass) ----
#pragma unroll
            for (int kk = 0; kk < 4; kk++) {
#pragma unroll
                for (int np = 0; np < 8; np++) {
                    uint32_t bvh[4], bvl[4];
                    uint32_t vo = (uint32_t)((np * 16 + r16) * 144 + kk * 32 + khB);
                    LDSM4(bvh, VB + vo);
                    LDSM4(bvl, VB + 18432 + vo);
#pragma unroll
                    for (int hs = 0; hs < 2; hs++) {
                        const int nd = np * 2 + hs;
                        MMA16816(o[nd], aph[kk], bvh[hs], bvh[2 + hs]);
                        MMA16816(o[nd], aph[kk], bvl[hs], bvl[2 + hs]);
                        MMA16816(o[nd], apl[kk], bvh[hs], bvh[2 + hs]);
                    }
                }
            }
        }
        __syncthreads();
    }

    // ---- epilogue: normalize and write split-bf16 directly ----
    float inv0 = 1.f / l_run[0], inv1 = 1.f / l_run[1];
    const size_t r0o = (size_t)(q0 + wm * 16 + g) * EMB + h * HDv;
    const size_t r1o = (size_t)(q0 + wm * 16 + g + 8) * EMB + h * HDv;
#pragma unroll
    for (int nd = 0; nd < 16; nd++) {
        int c = nd * 8 + tig * 2;
        uint32_t ph, pl;
        split2(o[nd][0] * inv0, o[nd][1] * inv0, ph, pl);
        *(uint32_t*)(g_aoh + r0o + c) = ph;
        *(uint32_t*)(g_aol + r0o + c) = pl;
        split2(o[nd][2] * inv1, o[nd][3] * inv1, ph, pl);
        *(uint32_t*)(g_aoh + r1o + c) = ph;
        *(uint32_t*)(g_aol + r1o + c) = pl;
    }
}

// ------------------- launch -------------------
extern "C" void kernel_launch(void* const* d_in, const int* in_sizes, int n_in,
                              void* d_out, int out_size)
{
    const float* hs = (const float*)d_in[0];
    const float* Wq = (const float*)d_in[1];
    const float* Wk = (const float*)d_in[2];
    const float* Wv = (const float*)d_in[3];
    const float* Wo = (const float*)d_in[4];
    const int*   pos = (const int*)d_in[6];
    float* out = (float*)d_out;

    float *p_q, *p_k, *p_v;
    cudaGetSymbolAddress((void**)&p_q,  g_q);
    cudaGetSymbolAddress((void**)&p_k,  g_k);
    cudaGetSymbolAddress((void**)&p_v,  g_v);
    __nv_bfloat16 *p_ah, *p_al, *p_aoh, *p_aol;
    __nv_bfloat16 *p_wqh, *p_wql, *p_wkh, *p_wkl, *p_wvh, *p_wvl, *p_woh, *p_wol;
    __nv_bfloat16 *p_qh, *p_kh, *p_vth, *p_vtl;
    cudaGetSymbolAddress((void**)&p_ah,  g_ah);
    cudaGetSymbolAddress((void**)&p_al,  g_al);
    cudaGetSymbolAddress((void**)&p_aoh, g_aoh);
    cudaGetSymbolAddress((void**)&p_aol, g_aol);
    cudaGetSymbolAddress((void**)&p_wqh, g_wqh);
    cudaGetSymbolAddress((void**)&p_wql, g_wql);
    cudaGetSymbolAddress((void**)&p_wkh, g_wkh);
    cudaGetSymbolAddress((void**)&p_wkl, g_wkl);
    cudaGetSymbolAddress((void**)&p_wvh, g_wvh);
    cudaGetSymbolAddress((void**)&p_wvl, g_wvl);
    cudaGetSymbolAddress((void**)&p_woh, g_woh);
    cudaGetSymbolAddress((void**)&p_wol, g_wol);
    cudaGetSymbolAddress((void**)&p_qh,  g_qh);
    cudaGetSymbolAddress((void**)&p_kh,  g_kh);
    cudaGetSymbolAddress((void**)&p_vth, g_vth);
    cudaGetSymbolAddress((void**)&p_vtl, g_vtl);

    cudaFuncSetAttribute(tgemm_kernel<true>,  cudaFuncAttributeMaxDynamicSharedMemorySize, TG_SMEM_SPLIT);
    cudaFuncSetAttribute(tgemm_kernel<false>, cudaFuncAttributeMaxDynamicSharedMemorySize, TG_SMEM_FAST);
    cudaFuncSetAttribute(flash_mma_kernel, cudaFuncAttributeMaxDynamicSharedMemorySize, FA2_SMEM);

    // 0) split conversions
    conv_split_kernel<<<(S_LEN * EMB / 4 + 255) / 256, 256>>>(hs, p_ah, p_al, S_LEN * EMB / 4);
    conv_split_t_kernel<<<dim3(EMB / 32, EMB / 32), dim3(32, 8)>>>(Wq, p_wqh, p_wql, EMB, EMB);
    conv_split_t_kernel<<<dim3(KVD / 32, EMB / 32), dim3(32, 8)>>>(Wk, p_wkh, p_wkl, EMB, KVD);
    conv_split_t_kernel<<<dim3(KVD / 32, EMB / 32), dim3(32, 8)>>>(Wv, p_wvh, p_wvl, EMB, KVD);
    conv_split_t_kernel<<<dim3(EMB / 32, EMB / 32), dim3(32, 8)>>>(Wo, p_woh, p_wol, EMB, EMB);

    // 1) projections (HMMA): Q/K single-pass bf16, V 3-pass
    tgemm_kernel<false><<<dim3(EMB / 128, S_LEN / 128), 256, TG_SMEM_FAST>>>(p_ah, nullptr, p_wqh, nullptr, p_q, EMB, EMB);
    tgemm_kernel<false><<<dim3(KVD / 128, S_LEN / 128), 256, TG_SMEM_FAST>>>(p_ah, nullptr, p_wkh, nullptr, p_k, KVD, EMB);
    tgemm_kernel<true> <<<dim3(KVD / 128, S_LEN / 128), 256, TG_SMEM_SPLIT>>>(p_ah, p_al, p_wvh, p_wvl, p_v, KVD, EMB);

    // 2) RoPE -> bf16 attention operands (fp32 table; Q/K hi-only; V split)
    rope_table_kernel<<<S_LEN, 64>>>(pos);
    rope_bf16_kernel<<<dim3(S_LEN, NHEADS), 64>>>(p_q, p_qh, EMB, 0.08838834764831845f);
    rope_bf16_kernel<<<dim3(S_LEN, NKVH),  64>>>(p_k, p_kh, KVD, 1.0f);
    conv_split_t_kernel<<<dim3(KVD / 32, S_LEN / 32), dim3(32, 8)>>>(p_v, p_vth, p_vtl, S_LEN, KVD);

    // 3) causal flash attention (HMMA, BM=128, bf16 QK^T; writes split-bf16 ao)
    flash_mma_kernel<<<dim3(S_LEN / 128, NHEADS), 256, FA2_SMEM>>>();

    // 4) output projection (HMMA, 3-pass) — consumes flash's split output directly
    tgemm_kernel<true><<<dim3(EMB / 128, S_LEN / 128), 256, TG_SMEM_SPLIT>>>(p_aoh, p_aol, p_woh, p_wol, out, EMB, EMB);
}

// round 17
// speedup vs baseline: 1.6249x; 1.0182x over previous
#include <cuda_runtime.h>
#include <cuda_bf16.h>
#include <math.h>
#include <stdint.h>

#define S_LEN 4096
#define EMB   2048
#define NHEADS 16
#define NKVH   4
#define HDv    128
#define KVD    (NKVH * HDv)   // 512

// ------------------- scratch (device globals; no allocations) -------------------
__device__ float g_q [S_LEN * EMB];
__device__ float g_k [S_LEN * KVD];
__device__ float g_v [S_LEN * KVD];
__device__ float g_cos[S_LEN * 64];
__device__ float g_sin[S_LEN * 64];
// split-bf16 operands (GEMM)
__device__ __nv_bfloat16 g_ah [S_LEN * EMB], g_al [S_LEN * EMB];
__device__ __nv_bfloat16 g_aoh[S_LEN * EMB], g_aol[S_LEN * EMB];   // flash writes these directly
__device__ __nv_bfloat16 g_wqh[EMB * EMB], g_wql[EMB * EMB];
__device__ __nv_bfloat16 g_wkh[KVD * EMB], g_wkl[KVD * EMB];
__device__ __nv_bfloat16 g_wvh[KVD * EMB], g_wvl[KVD * EMB];
__device__ __nv_bfloat16 g_woh[EMB * EMB], g_wol[EMB * EMB];
// attention operands: Q/K hi-only; V split hi/lo
__device__ __nv_bfloat16 g_qh [NHEADS * S_LEN * HDv];                            // [h][s][d] (pre-scaled by log2e/sqrt(HD))
__device__ __nv_bfloat16 g_kh [NKVH * S_LEN * HDv];                              // [kvh][s][d]
__device__ __nv_bfloat16 g_vth[NKVH * HDv * S_LEN], g_vtl[NKVH * HDv * S_LEN];   // [kvh][d][s]

// ------------------- helpers -------------------
__device__ __forceinline__ uint32_t smem_u32(const void* p) {
    uint32_t a;
    asm("{ .reg .u64 t; cvta.to.shared.u64 t, %1; cvt.u32.u64 %0, t; }" : "=r"(a) : "l"(p));
    return a;
}
#define SMEM_SWZ(off) ((off) ^ (((off) >> 3) & 0x70))

#define LDSM4(r, a) \
    asm volatile("ldmatrix.sync.aligned.m8n8.x4.shared.b16 {%0,%1,%2,%3}, [%4];" \
        : "=r"((r)[0]), "=r"((r)[1]), "=r"((r)[2]), "=r"((r)[3]) : "r"(a))

#define MMA16816(d, a, b0v, b1v) \
    asm volatile("mma.sync.aligned.m16n8k16.row.col.f32.bf16.bf16.f32 " \
        "{%0,%1,%2,%3}, {%4,%5,%6,%7}, {%8,%9}, {%0,%1,%2,%3};" \
        : "+f"((d)[0]), "+f"((d)[1]), "+f"((d)[2]), "+f"((d)[3]) \
        : "r"((a)[0]), "r"((a)[1]), "r"((a)[2]), "r"((a)[3]), "r"(b0v), "r"(b1v))

#define CP_ASYNC16(s, g) \
    asm volatile("cp.async.cg.shared.global [%0], [%1], 16;" :: "r"(s), "l"(g))
#define CP_COMMIT() asm volatile("cp.async.commit_group;" ::: "memory")
#define CP_WAIT1()  asm volatile("cp.async.wait_group 1;" ::: "memory")
#define CP_WAIT0()  asm volatile("cp.async.wait_group 0;" ::: "memory")

// split a,b into packed bf16x2 hi and lo (lower half = a, upper half = b)
__device__ __forceinline__ void split2(float a, float b, uint32_t& ph, uint32_t& pl) {
    float ha = __bfloat162float(__float2bfloat16(a));
    float hb = __bfloat162float(__float2bfloat16(b));
    asm("cvt.rn.bf16x2.f32 %0, %1, %2;" : "=r"(ph) : "f"(hb), "f"(ha));
    asm("cvt.rn.bf16x2.f32 %0, %1, %2;" : "=r"(pl) : "f"(b - hb), "f"(a - ha));
}

// ------------------- split conversion: fp32 -> (hi, lo) bf16 -------------------
__global__ __launch_bounds__(256) void conv_split_kernel(
    const float* __restrict__ src, __nv_bfloat16* __restrict__ hi,
    __nv_bfloat16* __restrict__ lo, int n4)
{
    int i = blockIdx.x * 256 + threadIdx.x;
    if (i >= n4) return;
    float4 v = ((const float4*)src)[i];
    __nv_bfloat16 h0 = __float2bfloat16(v.x), h1 = __float2bfloat16(v.y);
    __nv_bfloat16 h2 = __float2bfloat16(v.z), h3 = __float2bfloat16(v.w);
    __nv_bfloat16 l0 = __float2bfloat16(v.x - __bfloat162float(h0));
    __nv_bfloat16 l1 = __float2bfloat16(v.y - __bfloat162float(h1));
    __nv_bfloat16 l2 = __float2bfloat16(v.z - __bfloat162float(h2));
    __nv_bfloat16 l3 = __float2bfloat16(v.w - __bfloat162float(h3));
    ((__nv_bfloat162*)hi)[i * 2]     = __nv_bfloat162(h0, h1);
    ((__nv_bfloat162*)hi)[i * 2 + 1] = __nv_bfloat162(h2, h3);
    ((__nv_bfloat162*)lo)[i * 2]     = __nv_bfloat162(l0, l1);
    ((__nv_bfloat162*)lo)[i * 2 + 1] = __nv_bfloat162(l2, l3);
}

// transpose + split: src [R',C] fp32 -> hi/lo [C,R] bf16
__global__ __launch_bounds__(256) void conv_split_t_kernel(
    const float* __restrict__ src, __nv_bfloat16* __restrict__ hi,
    __nv_bfloat16* __restrict__ lo, int R, int C)
{
    __shared__ float T[32][33];
    const int x = threadIdx.x, y = threadIdx.y;     // block (32, 8)
    const int c0 = blockIdx.x * 32, r0 = blockIdx.y * 32;
#pragma unroll
    for (int i = 0; i < 4; i++)
        T[y + 8 * i][x] = src[(size_t)(r0 + y + 8 * i) * C + c0 + x];
    __syncthreads();
#pragma unroll
    for (int i = 0; i < 4; i++) {
        int r = y + 8 * i;
        float v = T[x][r];
        __nv_bfloat16 h = __float2bfloat16(v);
        __nv_bfloat16 l = __float2bfloat16(v - __bfloat162float(h));
        size_t o = (size_t)(c0 + r) * R + r0 + x;
        hi[o] = h; lo[o] = l;
    }
}

// ------------------- mma.sync bf16 GEMM: SPLIT=3-pass fp32-accurate, !SPLIT=1-pass ----
#define TG_SMEM_SPLIT  (2 * 65536)
#define TG_SMEM_FAST   (2 * 32768)

template<bool SPLIT>
__global__ __launch_bounds__(256, SPLIT ? 1 : 2)
void tgemm_kernel(const __nv_bfloat16* __restrict__ Ah, const __nv_bfloat16* __restrict__ Al,
                  const __nv_bfloat16* __restrict__ Bh, const __nv_bfloat16* __restrict__ Bl,
                  float* __restrict__ C, int N, int K)
{
    constexpr uint32_t STAGE = SPLIT ? 65536 : 32768;
    constexpr uint32_t BOFF  = SPLIT ? 32768 : 16384;
    extern __shared__ char dsm[];
    const uint32_t sb = smem_u32(dsm);
    const int tid = threadIdx.x;
    const int wid = tid >> 5, lane = tid & 31;
    const int warp_m = wid >> 2, warp_n = wid & 3;
    const int row0 = blockIdx.y * 128;
    const int col0 = blockIdx.x * 128;

    const int crow = tid >> 3;
    const int cu = tid & 7;

    const int r16 = lane & 15;
    const int khB = (lane >> 4) * 16;
    const int a_row = warp_m * 64 + r16;
    const int b_row = warp_n * 32 + r16;

    float d[4][4][4];
#pragma unroll
    for (int mf = 0; mf < 4; mf++)
#pragma unroll
        for (int nf = 0; nf < 4; nf++)
#pragma unroll
            for (int j = 0; j < 4; j++) d[mf][nf][j] = 0.f;

    const int nch = K >> 6;

    {
        uint32_t s0 = sb;
#pragma unroll
        for (int t = 0; t < 4; t++) {
            int row = crow + t * 32;
            uint32_t so = SMEM_SWZ((uint32_t)(row * 128 + cu * 16));
            size_t ga = (size_t)(row0 + row) * K + cu * 8;
            size_t gb = (size_t)(col0 + row) * K + cu * 8;
            CP_ASYNC16(s0 + so,        (const char*)(Ah + ga));
            CP_ASYNC16(s0 + BOFF + so, (const char*)(Bh + gb));
            if (SPLIT) {
                CP_ASYNC16(s0 + 16384 + so, (const char*)(Al + ga));
                CP_ASYNC16(s0 + 49152 + so, (const char*)(Bl + gb));
            }
        }
        CP_COMMIT();
    }

    for (int c = 0; c < nch; c++) {
        if (c + 1 < nch) {
            uint32_t s1 = sb + ((c + 1) & 1) * STAGE;
            const int ke = (c + 1) * 64;
#pragma unroll
            for (int t = 0; t < 4; t++) {
                int row = crow + t * 32;
                uint32_t so = SMEM_SWZ((uint32_t)(row * 128 + cu * 16));
                size_t ga = (size_t)(row0 + row) * K + ke + cu * 8;
                size_t gb = (size_t)(col0 + row) * K + ke + cu * 8;
                CP_ASYNC16(s1 + so,        (const char*)(Ah + ga));
                CP_ASYNC16(s1 + BOFF + so, (const char*)(Bh + gb));
                if (SPLIT) {
                    CP_ASYNC16(s1 + 16384 + so, (const char*)(Al + ga));
                    CP_ASYNC16(s1 + 49152 + so, (const char*)(Bl + gb));
                }
            }
            CP_COMMIT();
            CP_WAIT1();
        } else {
            CP_WAIT0();
        }
        __syncthreads();

        const uint32_t buf = sb + (c & 1) * STAGE;
#pragma unroll
        for (int ks = 0; ks < 4; ks++) {
            uint32_t ah[4][4], al[4][4], bh[2][4], bl[2][4];
#pragma unroll
            for (int mf = 0; mf < 4; mf++) {
                uint32_t off = SMEM_SWZ((uint32_t)((a_row + mf * 16) * 128 + ks * 32 + khB));
                LDSM4(ah[mf], buf + off);
                if (SPLIT) LDSM4(al[mf], buf + 16384 + off);
            }
#pragma unroll
            for (int np = 0; np < 2; np++) {
                uint32_t off = SMEM_SWZ((uint32_t)((b_row + np * 16) * 128 + ks * 32 + khB));
                LDSM4(bh[np], buf + BOFF + off);
                if (SPLIT) LDSM4(bl[np], buf + 49152 + off);
            }
#pragma unroll
            for (int mf = 0; mf < 4; mf++)
#pragma unroll
                for (int nf = 0; nf < 4; nf++) {
                    const int np = nf >> 1, h = nf & 1;
                    MMA16816(d[mf][nf], ah[mf], bh[np][h], bh[np][2 + h]);
                    if (SPLIT) {
                        MMA16816(d[mf][nf], ah[mf], bl[np][h], bl[np][2 + h]);
                        MMA16816(d[mf][nf], al[mf], bh[np][h], bh[np][2 + h]);
                    }
                }
        }
        __syncthreads();
    }

    const int g = lane >> 2, tig = lane & 3;
#pragma unroll
    for (int mf = 0; mf < 4; mf++)
#pragma unroll
        for (int nf = 0; nf < 4; nf++) {
            int row = row0 + warp_m * 64 + mf * 16 + g;
            int col = col0 + warp_n * 32 + nf * 8 + tig * 2;
            *(float2*)&C[(size_t)row * N + col] = make_float2(d[mf][nf][0], d[mf][nf][1]);
            *(float2*)&C[(size_t)(row + 8) * N + col] = make_float2(d[mf][nf][2], d[mf][nf][3]);
        }
}

// ------------------- RoPE table (fp32, replicating reference op order) -------------------
__global__ void rope_table_kernel(const int* __restrict__ pos_ids) {
    int s = blockIdx.x, d = threadIdx.x;   // d in [0,64)
    float x = (float)d / 64.0f;
    float inv = 1.0f / powf(1000000.0f, x);
    float ang = (float)pos_ids[s] * inv;
    float sn, c;
    sincosf(ang, &sn, &c);
    g_cos[s * 64 + d] = c;
    g_sin[s * 64 + d] = sn;
}

// ------------------- RoPE apply -> bf16 (hi only) [h][s][d] -------------------
__global__ void rope_bf16_kernel(const float* __restrict__ src,
                                 __nv_bfloat16* __restrict__ oh,
                                 int ncols, float sc)
{
    int s = blockIdx.x, h = blockIdx.y, d = threadIdx.x;  // d in [0,64)
    float c  = g_cos[s * 64 + d];
    float sn = g_sin[s * 64 + d];
    const float* p = src + (size_t)s * ncols + h * HDv;
    float x0 = p[d], x1 = p[d + 64];
    size_t o = ((size_t)h * S_LEN + s) * HDv + d;
    oh[o]      = __float2bfloat16((x0 * c - x1 * sn) * sc);
    oh[o + 64] = __float2bfloat16((x1 * c + x0 * sn) * sc);
}

// ------------------- Flash attention: mma.sync, BM=128, 3-stage pipeline ----------
// Q pre-scaled by log2e/sqrt(HD); softmax in base-2 (exp2f).
// smem: Qh [0,34816) pitch 272; K: 3 x 17408 at 34816; V: 3 x 36864 at 87040.
#define FQOFF   0
#define FKOFF   34816
#define FKSTR   17408
#define FVOFF   87040
#define FVSTR   36864
#define FA2_SMEM 197632

__global__ __launch_bounds__(256, 1) void flash_mma_kernel() {
    extern __shared__ char fsm[];
    const uint32_t sb = smem_u32(fsm);
    const int tid = threadIdx.x;
    const int wm = tid >> 5, lane = tid & 31;
    const int g = lane >> 2, tig = lane & 3;
    const int r16 = lane & 15;
    const int khB = (lane >> 4) * 16;
    const int h = blockIdx.y;
    const int qb = (int)gridDim.x - 1 - (int)blockIdx.x;  // long CTAs first
    const int q0 = qb * 128;
    const int kvh = h >> 2;

    const char* qhp = (const char*)(g_qh  + ((size_t)h * S_LEN + q0) * HDv);
    const char* khp = (const char*)(g_kh  + (size_t)kvh * S_LEN * HDv);
    const char* vhp = (const char*)(g_vth + (size_t)kvh * HDv * S_LEN);
    const char* vlp = (const char*)(g_vtl + (size_t)kvh * HDv * S_LEN);

    const int nkb = 2 * qb + 2;

    // prologue: Q + kv-block 0 (group 0)
#pragma unroll
    for (int t = 0; t < 8; t++) {
        int idx = tid + t * 256;
        int row = idx >> 4, u = idx & 15;
        CP_ASYNC16(sb + FQOFF + row * 272 + u * 16, qhp + row * 256 + u * 16);
    }
#pragma unroll
    for (int t = 0; t < 4; t++) {
        int idx = tid + t * 256;
        int row = idx >> 4, u = idx & 15;
        CP_ASYNC16(sb + FKOFF + row * 272 + u * 16, khp + row * 256 + u * 16);
        int vr = idx >> 3, vu = idx & 7;
        CP_ASYNC16(sb + FVOFF + vr * 144 + vu * 16,         vhp + (size_t)vr * (S_LEN * 2) + vu * 16);
        CP_ASYNC16(sb + FVOFF + 18432 + vr * 144 + vu * 16, vlp + (size_t)vr * (S_LEN * 2) + vu * 16);
    }
    CP_COMMIT();
    // kv-block 1 (group 1)
    if (1 < nkb) {
        uint32_t KB = sb + FKOFF + FKSTR;
        uint32_t VB = sb + FVOFF + FVSTR;
#pragma unroll
        for (int t = 0; t < 4; t++) {
            int idx = tid + t * 256;
            int row = idx >> 4, u = idx & 15;
            CP_ASYNC16(KB + row * 272 + u * 16, khp + (size_t)(64 + row) * 256 + u * 16);
            int vr = idx >> 3, vu = idx & 7;
            CP_ASYNC16(VB + vr * 144 + vu * 16,         vhp + (size_t)vr * (S_LEN * 2) + 128 + vu * 16);
            CP_ASYNC16(VB + 18432 + vr * 144 + vu * 16, vlp + (size_t)vr * (S_LEN * 2) + 128 + vu * 16);
        }
        CP_COMMIT();
    }

    float m_run[2] = {-1e30f, -1e30f};
    float l_run[2] = {0.f, 0.f};
    float o[16][4];
#pragma unroll
    for (int i = 0; i < 16; i++) { o[i][0] = o[i][1] = o[i][2] = o[i][3] = 0.f; }

    for (int kb = 0; kb < nkb; kb++) {
        // wait for stage kb's data (allow 1 pending group if more were issued)
        if (kb + 1 < nkb) { CP_WAIT1(); } else { CP_WAIT0(); }
        __syncthreads();   // data visible to all warps; all warps done with stage (kb-1)%3

        // issue kv-block kb+2 into stage (kb+2)%3 (== (kb-1)%3, now safe)
        if (kb + 2 < nkb) {
            const int sti = (kb + 2) % 3;
            const size_t k0n = (size_t)(kb + 2) * 64;
            uint32_t KB = sb + FKOFF + sti * FKSTR;
            uint32_t VB = sb + FVOFF + sti * FVSTR;
#pragma unroll
            for (int t = 0; t < 4; t++) {
                int idx = tid + t * 256;
                int row = idx >> 4, u = idx & 15;
                CP_ASYNC16(KB + row * 272 + u * 16, khp + (k0n + row) * 256 + u * 16);
                int vr = idx >> 3, vu = idx & 7;
                CP_ASYNC16(VB + vr * 144 + vu * 16,         vhp + (size_t)vr * (S_LEN * 2) + k0n * 2 + vu * 16);
                CP_ASYNC16(VB + 18432 + vr * 144 + vu * 16, vlp + (size_t)vr * (S_LEN * 2) + k0n * 2 + vu * 16);
            }
            CP_COMMIT();
        }

        const int k0 = kb * 64;
        if (k0 <= q0 + wm * 16 + 15) {
            const int stc = kb % 3;
            const uint32_t KB = sb + FKOFF + stc * FKSTR;
            const uint32_t VB = sb + FVOFF + stc * FVSTR;

            // ---- S' = (Q*log2e/sqrt(d)) K^T (single-pass bf16) ----
            float s[8][4];
#pragma unroll
            for (int nf = 0; nf < 8; nf++) s[nf][0] = s[nf][1] = s[nf][2] = s[nf][3] = 0.f;
#pragma unroll
            for (int ks = 0; ks < 8; ks++) {
                uint32_t aqh[4], bkh[4][4];
                uint32_t qo = (uint32_t)((wm * 16 + r16) * 272 + ks * 32 + khB);
                LDSM4(aqh, sb + FQOFF + qo);
#pragma unroll
                for (int np = 0; np < 4; np++) {
                    uint32_t ko = (uint32_t)((np * 16 + r16) * 272 + ks * 32 + khB);
                    LDSM4(bkh[np], KB + ko);
                }
#pragma unroll
                for (int nf = 0; nf < 8; nf++) {
                    const int np = nf >> 1, hs = nf & 1;
                    MMA16816(s[nf], aqh, bkh[np][hs], bkh[np][2 + hs]);
                }
            }

            if (kb >= 2 * qb) {
#pragma unroll
                for (int nf = 0; nf < 8; nf++)
#pragma unroll
                    for (int j = 0; j < 4; j++) {
                        int r = q0 + wm * 16 + g + ((j >> 1) << 3);
                        int c = k0 + nf * 8 + tig * 2 + (j & 1);
                        if (c > r) s[nf][j] = -1e30f;
                    }
            }

            // ---- warp-local online softmax (base-2) ----
            float rmx0 = -1e30f, rmx1 = -1e30f;
#pragma unroll
            for (int nf = 0; nf < 8; nf++) {
                rmx0 = fmaxf(rmx0, fmaxf(s[nf][0], s[nf][1]));
                rmx1 = fmaxf(rmx1, fmaxf(s[nf][2], s[nf][3]));
            }
            rmx0 = fmaxf(rmx0, __shfl_xor_sync(0xffffffffu, rmx0, 1));
            rmx0 = fmaxf(rmx0, __shfl_xor_sync(0xffffffffu, rmx0, 2));
            rmx1 = fmaxf(rmx1, __shfl_xor_sync(0xffffffffu, rmx1, 1));
            rmx1 = fmaxf(rmx1, __shfl_xor_sync(0xffffffffu, rmx1, 2));
            float mn0 = fmaxf(m_run[0], rmx0);
            float mn1 = fmaxf(m_run[1], rmx1);
            float fs0 = exp2f(m_run[0] - mn0);
            float fs1 = exp2f(m_run[1] - mn1);
            m_run[0] = mn0; m_run[1] = mn1;

            float sum0 = 0.f, sum1 = 0.f;
#pragma unroll
            for (int nf = 0; nf < 8; nf++) {
                s[nf][0] = exp2f(s[nf][0] - mn0);
                s[nf][1] = exp2f(s[nf][1] - mn0);
                s[nf][2] = exp2f(s[nf][2] - mn1);
                s[nf][3] = exp2f(s[nf][3] - mn1);
                sum0 += s[nf][0] + s[nf][1];
                sum1 += s[nf][2] + s[nf][3];
            }
            sum0 += __shfl_xor_sync(0xffffffffu, sum0, 1);
            sum0 += __shfl_xor_sync(0xffffffffu, sum0, 2);
            sum1 += __shfl_xor_sync(0xffffffffu, sum1, 1);
            sum1 += __shfl_xor_sync(0xffffffffu, sum1, 2);
            l_run[0] = l_run[0] * fs0 + sum0;
            l_run[1] = l_run[1] * fs1 + sum1;

#pragma unroll
            for (int i = 0; i < 16; i++) {
                o[i][0] *= fs0; o[i][1] *= fs0; o[i][2] *= fs1; o[i][3] *= fs1;
            }

            // ---- P A-frags (register reuse, split hi/lo) ----
            uint32_t aph[4][4], apl[4][4];
#pragma unroll
            for (int kk = 0; kk < 4; kk++) {
                const int nfA = 2 * kk, nfB = 2 * kk + 1;
                split2(s[nfA][0], s[nfA][1], aph[kk][0], apl[kk][0]);
                split2(s[nfA][2], s[nfA][3], aph[kk][1], apl[kk][1]);
                split2(s[nfB][0], s[nfB][1], aph[kk][2], apl[kk][2]);
                split2(s[nfB][2], s[nfB][3], aph[kk][3], apl[kk][3]);
            }

            // ---- O += P V (split 3-pass) ----
#pragma unroll
            for (int kk = 0; kk < 4; kk++) {
#pragma unroll
                for (int np = 0; np < 8; np++) {
                    uint32_t bvh[4], bvl[4];
                    uint32_t vo = (uint32_t)((np * 16 + r16) * 144 + kk * 32 + khB);
                    LDSM4(bvh, VB + vo);
                    LDSM4(bvl, VB + 18432 + vo);
#pragma unroll
                    for (int hs = 0; hs < 2; hs++) {
                        const int nd = np * 2 + hs;
                        MMA16816(o[nd], aph[kk], bvh[hs], bvh[2 + hs]);
                        MMA16816(o[nd], aph[kk], bvl[hs], bvl[2 + hs]);
                        MMA16816(o[nd], apl[kk], bvh[hs], bvh[2 + hs]);
                    }
                }
            }
        }
        // no trailing barrier: the top-of-loop barrier protects buffer reuse
    }

    // ---- epilogue: normalize and write split-bf16 directly ----
    float inv0 = 1.f / l_run[0], inv1 = 1.f / l_run[1];
    const size_t r0o = (size_t)(q0 + wm * 16 + g) * EMB + h * HDv;
    const size_t r1o = (size_t)(q0 + wm * 16 + g + 8) * EMB + h * HDv;
#pragma unroll
    for (int nd = 0; nd < 16; nd++) {
        int c = nd * 8 + tig * 2;
        uint32_t ph, pl;
        split2(o[nd][0] * inv0, o[nd][1] * inv0, ph, pl);
        *(uint32_t*)(g_aoh + r0o + c) = ph;
        *(uint32_t*)(g_aol + r0o + c) = pl;
        split2(o[nd][2] * inv1, o[nd][3] * inv1, ph, pl);
        *(uint32_t*)(g_aoh + r1o + c) = ph;
        *(uint32_t*)(g_aol + r1o + c) = pl;
    }
}

// ------------------- launch -------------------
extern "C" void kernel_launch(void* const* d_in, const int* in_sizes, int n_in,
                              void* d_out, int out_size)
{
    const float* hs = (const float*)d_in[0];
    const float* Wq = (const float*)d_in[1];
    const float* Wk = (const float*)d_in[2];
    const float* Wv = (const float*)d_in[3];
    const float* Wo = (const float*)d_in[4];
    const int*   pos = (const int*)d_in[6];
    float* out = (float*)d_out;

    float *p_q, *p_k, *p_v;
    cudaGetSymbolAddress((void**)&p_q,  g_q);
    cudaGetSymbolAddress((void**)&p_k,  g_k);
    cudaGetSymbolAddress((void**)&p_v,  g_v);
    __nv_bfloat16 *p_ah, *p_al, *p_aoh, *p_aol;
    __nv_bfloat16 *p_wqh, *p_wql, *p_wkh, *p_wkl, *p_wvh, *p_wvl, *p_woh, *p_wol;
    __nv_bfloat16 *p_qh, *p_kh, *p_vth, *p_vtl;
    cudaGetSymbolAddress((void**)&p_ah,  g_ah);
    cudaGetSymbolAddress((void**)&p_al,  g_al);
    cudaGetSymbolAddress((void**)&p_aoh, g_aoh);
    cudaGetSymbolAddress((void**)&p_aol, g_aol);
    cudaGetSymbolAddress((void**)&p_wqh, g_wqh);
    cudaGetSymbolAddress((void**)&p_wql, g_wql);
    cudaGetSymbolAddress((void**)&p_wkh, g_wkh);
    cudaGetSymbolAddress((void**)&p_wkl, g_wkl);
    cudaGetSymbolAddress((void**)&p_wvh, g_wvh);
    cudaGetSymbolAddress((void**)&p_wvl, g_wvl);
    cudaGetSymbolAddress((void**)&p_woh, g_woh);
    cudaGetSymbolAddress((void**)&p_wol, g_wol);
    cudaGetSymbolAddress((void**)&p_qh,  g_qh);
    cudaGetSymbolAddress((void**)&p_kh,  g_kh);
    cudaGetSymbolAddress((void**)&p_vth, g_vth);
    cudaGetSymbolAddress((void**)&p_vtl, g_vtl);

    cudaFuncSetAttribute(tgemm_kernel<true>,  cudaFuncAttributeMaxDynamicSharedMemorySize, TG_SMEM_SPLIT);
    cudaFuncSetAttribute(tgemm_kernel<false>, cudaFuncAttributeMaxDynamicSharedMemorySize, TG_SMEM_FAST);
    cudaFuncSetAttribute(flash_mma_kernel, cudaFuncAttributeMaxDynamicSharedMemorySize, FA2_SMEM);

    // 0) split conversions
    conv_split_kernel<<<(S_LEN * EMB / 4 + 255) / 256, 256>>>(hs, p_ah, p_al, S_LEN * EMB / 4);
    conv_split_t_kernel<<<dim3(EMB / 32, EMB / 32), dim3(32, 8)>>>(Wq, p_wqh, p_wql, EMB, EMB);
    conv_split_t_kernel<<<dim3(KVD / 32, EMB / 32), dim3(32, 8)>>>(Wk, p_wkh, p_wkl, EMB, KVD);
    conv_split_t_kernel<<<dim3(KVD / 32, EMB / 32), dim3(32, 8)>>>(Wv, p_wvh, p_wvl, EMB, KVD);
    conv_split_t_kernel<<<dim3(EMB / 32, EMB / 32), dim3(32, 8)>>>(Wo, p_woh, p_wol, EMB, EMB);

    // 1) projections (HMMA): Q/K single-pass bf16 (2 CTAs/SM), V 3-pass
    tgemm_kernel<false><<<dim3(EMB / 128, S_LEN / 128), 256, TG_SMEM_FAST>>>(p_ah, nullptr, p_wqh, nullptr, p_q, EMB, EMB);
    tgemm_kernel<false><<<dim3(KVD / 128, S_LEN / 128), 256, TG_SMEM_FAST>>>(p_ah, nullptr, p_wkh, nullptr, p_k, KVD, EMB);
    tgemm_kernel<true> <<<dim3(KVD / 128, S_LEN / 128), 256, TG_SMEM_SPLIT>>>(p_ah, p_al, p_wvh, p_wvl, p_v, KVD, EMB);

    // 2) RoPE -> bf16 attention operands; Q pre-scaled by log2e/sqrt(HD)
    rope_table_kernel<<<S_LEN, 64>>>(pos);
    rope_bf16_kernel<<<dim3(S_LEN, NHEADS), 64>>>(p_q, p_qh, EMB,
        0.08838834764831845f * 1.4426950408889634f);
    rope_bf16_kernel<<<dim3(S_LEN, NKVH),  64>>>(p_k, p_kh, KVD, 1.0f);
    conv_split_t_kernel<<<dim3(KVD / 32, S_LEN / 32), dim3(32, 8)>>>(p_v, p_vth, p_vtl, S_LEN, KVD);

    // 3) causal flash attention (HMMA, BM=128, 3-stage pipeline, base-2 softmax)
    flash_mma_kernel<<<dim3(S_LEN / 128, NHEADS), 256, FA2_SMEM>>>();

    // 4) output projection (HMMA, 3-pass) — consumes flash's split output directly
    tgemm_kernel<true><<<dim3(EMB / 128, S_LEN / 128), 256, TG_SMEM_SPLIT>>>(p_aoh, p_aol, p_woh, p_wol, out, EMB, EMB);
}